// round 8
// baseline (speedup 1.0000x reference)
#include <cuda_runtime.h>
#include <cuda_fp16.h>
#include <cstdint>
#include <cfloat>

// Problem constants
#define N_ROWS  131072
#define DIMS    64
#define KENT    4096
#define GM      128            // rows per CTA
#define GN      64             // codes per chunk
#define NCHUNK  (KENT / GN)    // 64
#define GBLOCKS (N_ROWS / GM)  // 1024
#define ETHREADS 256
#define EBLOCKS (N_ROWS / ETHREADS)
#define TAU1    0.03f          // fp16-gemm dist margin -> tier-1
#define TAU2    1e-3f          // fp32-mid dist margin  -> tier-2 (bit-exact)

// gemm smem: padded row stride 144B -> ldmatrix conflict-free
#define SROW    144
#define A_BYTES (GM * SROW)            // 18432
#define B_OFF   A_BYTES
#define B_BYTES (GN * SROW)            // 9216 per buffer
#define EN_OFF  (B_OFF + 2 * B_BYTES)
#define SMEM_TOTAL (EN_OFF + 2 * 256)  // 37376

// Scratch
__device__ __half g_bh[(size_t)KENT * DIMS];   // fp16 codebook, 512 KB
__device__ float g_enorm[KENT];
__device__ float g_en2[KENT];
__device__ float g_bsum[EBLOCKS];
__device__ int   g_idx[N_ROWS];
__device__ int   g_list[N_ROWS];
__device__ int   g_list2[N_ROWS];
__device__ int   g_cnt, g_cnt2;

// ---------------- helpers (plain sm_103-safe) ----------------
__device__ __forceinline__ uint32_t smem_u32(const void* p) {
    uint32_t a;
    asm("{ .reg .u64 t; cvta.to.shared.u64 t, %1; cvt.u32.u64 %0, t; }" : "=r"(a) : "l"(p));
    return a;
}
#define CP_ASYNC16(dst, src) \
    asm volatile("cp.async.cg.shared.global [%0], [%1], 16;" :: "r"(dst), "l"(src))
#define CP_COMMIT() asm volatile("cp.async.commit_group;" ::: "memory")
#define CP_WAIT(n)  asm volatile("cp.async.wait_group %0;" :: "n"(n) : "memory")

#define LDSM4(r0, r1, r2, r3, a) \
    asm volatile("ldmatrix.sync.aligned.m8n8.x4.shared.b16 {%0,%1,%2,%3}, [%4];" \
        : "=r"(r0), "=r"(r1), "=r"(r2), "=r"(r3) : "r"(a))

#define MMA16816(d, a, b0_, b1_) \
    asm volatile("mma.sync.aligned.m16n8k16.row.col.f32.f16.f16.f32 " \
        "{%0,%1,%2,%3}, {%4,%5,%6,%7}, {%8,%9}, {%0,%1,%2,%3};" \
        : "+f"((d)[0]), "+f"((d)[1]), "+f"((d)[2]), "+f"((d)[3]) \
        : "r"((a)[0]), "r"((a)[1]), "r"((a)[2]), "r"((a)[3]), "r"(b0_), "r"(b1_))

__device__ __forceinline__ unsigned long long pk2(float a, float b) {
    unsigned long long r;
    asm("mov.b64 %0, {%1, %2};" : "=l"(r) : "f"(a), "f"(b));
    return r;
}
__device__ __forceinline__ void upk2(unsigned long long v, float &a, float &b) {
    asm("mov.b64 {%0, %1}, %2;" : "=f"(a), "=f"(b) : "l"(v));
}
__device__ __forceinline__ void ffma2(unsigned long long &acc,
                                      unsigned long long a, unsigned long long b) {
    asm("fma.rn.f32x2 %0, %1, %2, %0;" : "+l"(acc) : "l"(a), "l"(b));
}
__device__ __forceinline__ void upd(float& b, float& b2, int& id, float g, int c) {
    if (g > b) { b2 = b; b = g; id = c; }
    else if (g > b2) { b2 = g; }
}

// ---------- kernel 0: codebook norms (fp64->fp32), -en/2 table, counter resets ----------
__global__ void vq_init(const float* __restrict__ cb) {
    int k = blockIdx.x * blockDim.x + threadIdx.x;
    if (k == 0) { g_cnt = 0; g_cnt2 = 0; }
    if (k < KENT) {
        const float4* p = (const float4*)(cb + (size_t)k * DIMS);
        double s = 0.0;
        #pragma unroll
        for (int i = 0; i < DIMS / 4; i++) {
            float4 v = p[i];
            s += (double)v.x * v.x + (double)v.y * v.y
               + (double)v.z * v.z + (double)v.w * v.w;
        }
        g_enorm[k] = (float)s;
        g_en2[k]   = (float)(-0.5 * s);
    }
}

// ---------- prep: cb -> fp16 ----------
__global__ void vq_prep_cb(const float* __restrict__ cb) {
    int i = blockIdx.x * blockDim.x + threadIdx.x;       // over all elems /4
    if (i < KENT * DIMS / 4) {
        float4 v = ((const float4*)cb)[i];
        __half2* o = (__half2*)(g_bh + (size_t)i * 4);
        o[0] = __floats2half2_rn(v.x, v.y);
        o[1] = __floats2half2_rn(v.z, v.w);
    }
}

// ---------- tier 0: single-pass fp16 HMMA GEMM + fused per-row argmax ----------
// g[m][n] = xh_m . eh_n - ||e_n||^2/2 ;  argmax_n g == argmin_n dist
__global__ __launch_bounds__(256, 3)
void vq_gemm(const float* __restrict__ x) {
    extern __shared__ char dsm[];
    const int tid  = threadIdx.x;
    const int wid  = tid >> 5;
    const int lane = tid & 31;

    const uint32_t S = smem_u32(dsm);

    // build A tile (fp16) in smem
    {
        const int rbase = blockIdx.x * GM;
        for (int idx = tid; idx < GM * DIMS; idx += 256) {
            int r = idx >> 6, d = idx & 63;
            float v = x[(size_t)(rbase + r) * DIMS + d];
            *(__half*)(dsm + r * SROW + 2 * d) = __float2half_rn(v);
        }
    }

    // prologue: chunk 0 B + en2
    {
        const char* Bg = (const char*)g_bh;
        for (int c = tid; c < GN * 8; c += 256) {
            int rowb = c >> 3, seg = c & 7;
            CP_ASYNC16(S + B_OFF + rowb * SROW + seg * 16, Bg + rowb * 128 + seg * 16);
        }
        if (tid < 16) CP_ASYNC16(S + EN_OFF + tid * 16, (const char*)g_en2 + tid * 16);
        CP_COMMIT();
        CP_WAIT(0);
    }
    __syncthreads();

    // hoist A fragments (4 k-steps x 4 regs)
    uint32_t af[4][4];
    {
        uint32_t a_base = S + (uint32_t)(wid * 16 + (lane & 15)) * SROW + (uint32_t)(lane >> 4) * 16;
        #pragma unroll
        for (int k = 0; k < 4; k++)
            LDSM4(af[k][0], af[k][1], af[k][2], af[k][3], a_base + k * 32);
    }

    const uint32_t n_part = (lane & 7) + ((lane >> 4) & 1) * 8;
    const uint32_t koff_b = ((lane >> 3) & 1) * 16;

    float bestA = -FLT_MAX, best2A = -FLT_MAX;
    float bestB = -FLT_MAX, best2B = -FLT_MAX;
    int   idxA = 0, idxB = 0;

    for (int i = 0; i < NCHUNK; i++) {
        const int buf = i & 1;

        if (i + 1 < NCHUNK) {
            const char* Bg = (const char*)(g_bh + (size_t)(i + 1) * GN * DIMS);
            uint32_t Bs = S + B_OFF + (buf ^ 1) * B_BYTES;
            for (int c = tid; c < GN * 8; c += 256) {
                int rowb = c >> 3, seg = c & 7;
                CP_ASYNC16(Bs + rowb * SROW + seg * 16, Bg + rowb * 128 + seg * 16);
            }
            if (tid < 16)
                CP_ASYNC16(S + EN_OFF + (buf ^ 1) * 256 + tid * 16,
                           (const char*)(g_en2 + (i + 1) * GN) + tid * 16);
            CP_COMMIT();
            CP_WAIT(1);
        } else {
            CP_WAIT(0);
        }
        __syncthreads();

        float d[8][4];
        #pragma unroll
        for (int t = 0; t < 8; t++)
            #pragma unroll
            for (int q = 0; q < 4; q++) d[t][q] = 0.0f;

        const uint32_t Bs = S + B_OFF + buf * B_BYTES;
        #pragma unroll
        for (int k = 0; k < 4; k++) {
            #pragma unroll
            for (int jp = 0; jp < 4; jp++) {
                uint32_t b0, b1, b2, b3;
                LDSM4(b0, b1, b2, b3, Bs + (16 * jp + n_part) * SROW + k * 32 + koff_b);
                MMA16816(d[2 * jp],     af[k], b0, b1);
                MMA16816(d[2 * jp + 1], af[k], b2, b3);
            }
        }

        const float* en2s = (const float*)(dsm + EN_OFF + buf * 256);
        const int c_base = i * GN + (lane & 3) * 2;
        #pragma unroll
        for (int t = 0; t < 8; t++) {
            int col0 = t * 8 + (lane & 3) * 2;
            float e0 = en2s[col0], e1 = en2s[col0 + 1];
            int c0 = c_base + t * 8;
            upd(bestA, best2A, idxA, d[t][0] + e0, c0);
            upd(bestA, best2A, idxA, d[t][1] + e1, c0 + 1);
            upd(bestB, best2B, idxB, d[t][2] + e0, c0);
            upd(bestB, best2B, idxB, d[t][3] + e1, c0 + 1);
        }
        __syncthreads();
    }

    #pragma unroll
    for (int s = 1; s <= 2; s <<= 1) {
        float ob  = __shfl_xor_sync(0xffffffffu, bestA,  s);
        float ob2 = __shfl_xor_sync(0xffffffffu, best2A, s);
        int   oi  = __shfl_xor_sync(0xffffffffu, idxA,   s);
        if (ob > bestA) { best2A = fmaxf(bestA, ob2); bestA = ob; idxA = oi; }
        else            { best2A = fmaxf(best2A, ob); }
        ob  = __shfl_xor_sync(0xffffffffu, bestB,  s);
        ob2 = __shfl_xor_sync(0xffffffffu, best2B, s);
        oi  = __shfl_xor_sync(0xffffffffu, idxB,   s);
        if (ob > bestB) { best2B = fmaxf(bestB, ob2); bestB = ob; idxB = oi; }
        else            { best2B = fmaxf(best2B, ob); }
    }

    if ((lane & 3) == 0) {
        const int q  = lane >> 2;
        const int mA = blockIdx.x * GM + wid * 16 + q;
        const int mB = mA + 8;
        g_idx[mA] = idxA;
        g_idx[mB] = idxB;
        if (2.0f * (bestA - best2A) < TAU1) { int s = atomicAdd(&g_cnt, 1); g_list[s] = mA; }
        if (2.0f * (bestB - best2B) < TAU1) { int s = atomicAdd(&g_cnt, 1); g_list[s] = mB; }
    }
}

// ---------- tier 1: fast fp32 (f32x2) rescore of tier-0 flagged rows, warp-per-row ----------
__global__ __launch_bounds__(256)
void vq_mid(const float* __restrict__ x, const float* __restrict__ cb) {
    const int lane = threadIdx.x & 31;
    const int gw   = (blockIdx.x * blockDim.x + threadIdx.x) >> 5;
    const int nw   = (gridDim.x * blockDim.x) >> 5;
    const int cnt  = g_cnt;

    for (int i = gw; i < cnt; i += nw) {
        const int row = g_list[i];

        // x row packed f32x2 in regs
        unsigned long long xr[DIMS / 2];
        {
            const float4* xp = (const float4*)(x + (size_t)row * DIMS);
            #pragma unroll
            for (int j = 0; j < DIMS / 4; j++) {
                float4 v = xp[j];
                xr[2 * j]     = pk2(v.x, v.y);
                xr[2 * j + 1] = pk2(v.z, v.w);
            }
        }
        // xnorm: fp64 warp reduction, rounded once
        double xs;
        {
            float a = __ldg(x + (size_t)row * DIMS + 2 * lane);
            float b = __ldg(x + (size_t)row * DIMS + 2 * lane + 1);
            xs = (double)a * a + (double)b * b;
            #pragma unroll
            for (int off = 16; off > 0; off >>= 1)
                xs += __shfl_xor_sync(0xffffffffu, xs, off);
        }
        const float xnorm = (float)xs;

        float best = FLT_MAX, best2 = FLT_MAX;
        int   bi   = 0x7fffffff;
        for (int k = lane; k < KENT; k += 32) {
            const ulonglong2* ep = (const ulonglong2*)(cb + (size_t)k * DIMS);
            unsigned long long a0 = 0ull, a1 = 0ull;
            #pragma unroll
            for (int j = 0; j < DIMS / 4; j++) {
                ulonglong2 e = ep[j];
                ffma2(a0, xr[2 * j],     e.x);
                ffma2(a1, xr[2 * j + 1], e.y);
            }
            float p0, p1, q0, q1;
            upk2(a0, p0, p1);
            upk2(a1, q0, q1);
            float dot  = (p0 + p1) + (q0 + q1);
            float dist = (xnorm + __ldg(&g_enorm[k])) - 2.0f * dot;
            if (dist < best) { best2 = best; best = dist; bi = k; }
            else if (dist < best2) { best2 = dist; }
        }
        // warp merge of (best, idx) with first-index tie-break + best2 tracking
        #pragma unroll
        for (int s = 1; s < 32; s <<= 1) {
            float ob  = __shfl_xor_sync(0xffffffffu, best,  s);
            float ob2 = __shfl_xor_sync(0xffffffffu, best2, s);
            int   oi  = __shfl_xor_sync(0xffffffffu, bi,    s);
            if (ob < best || (ob == best && oi < bi)) {
                best2 = fminf(best, ob2);
                best  = ob; bi = oi;
            } else {
                best2 = fminf(best2, ob);
            }
        }
        if (lane == 0) {
            g_idx[row] = bi;
            if (best2 - best < TAU2) {
                int s = atomicAdd(&g_cnt2, 1);
                g_list2[s] = row;
            }
        }
    }
}

// ---------- tier 2: bit-exact reference-emulating re-scan, warp-per-row ----------
// dist = fl( fl(xnorm + enorm_k) - 2 * dot32_k ), dot32_k = sequential ascending-d
// fp32 FMA chain; norms fp64-accumulated rounded once. (Validated: rel_err 6.7e-8.)
__global__ __launch_bounds__(256)
void vq_exact(const float* __restrict__ x, const float* __restrict__ cb) {
    const int lane = threadIdx.x & 31;
    const int gw   = (blockIdx.x * blockDim.x + threadIdx.x) >> 5;
    const int nw   = (gridDim.x * blockDim.x) >> 5;
    const int cnt  = g_cnt2;

    for (int i = gw; i < cnt; i += nw) {
        const int row = g_list2[i];

        float xr[DIMS];
        {
            const float4* xp = (const float4*)(x + (size_t)row * DIMS);
            #pragma unroll
            for (int j = 0; j < DIMS / 4; j++) {
                float4 v = xp[j];
                xr[4 * j] = v.x; xr[4 * j + 1] = v.y;
                xr[4 * j + 2] = v.z; xr[4 * j + 3] = v.w;
            }
        }
        double xs;
        {
            float a = __ldg(x + (size_t)row * DIMS + 2 * lane);
            float b = __ldg(x + (size_t)row * DIMS + 2 * lane + 1);
            xs = (double)a * a + (double)b * b;
            #pragma unroll
            for (int off = 16; off > 0; off >>= 1)
                xs += __shfl_xor_sync(0xffffffffu, xs, off);
        }
        const float xnorm = (float)xs;

        float best = FLT_MAX;
        int   bi   = 0x7fffffff;
        for (int k = lane; k < KENT; k += 32) {
            const float4* e4 = (const float4*)(cb + (size_t)k * DIMS);
            float acc = 0.0f;
            #pragma unroll
            for (int q = 0; q < DIMS / 4; q++) {
                float4 e = e4[q];
                acc = fmaf(xr[4 * q + 0], e.x, acc);
                acc = fmaf(xr[4 * q + 1], e.y, acc);
                acc = fmaf(xr[4 * q + 2], e.z, acc);
                acc = fmaf(xr[4 * q + 3], e.w, acc);
            }
            float t    = xnorm + __ldg(&g_enorm[k]);
            float dist = t - 2.0f * acc;
            if (dist < best) { best = dist; bi = k; }
        }
        #pragma unroll
        for (int s = 1; s < 32; s <<= 1) {
            float ob = __shfl_xor_sync(0xffffffffu, best, s);
            int   oi = __shfl_xor_sync(0xffffffffu, bi,   s);
            if (ob < best || (ob == best && oi < bi)) { best = ob; bi = oi; }
        }
        if (lane == 0) g_idx[row] = bi;
    }
}

// ---------- epilogue: gather winner, straight-through output, loss partials ----------
__global__ __launch_bounds__(ETHREADS)
void vq_epi(const float* __restrict__ x, const float* __restrict__ y,
            const float* __restrict__ cb, float* __restrict__ out) {
    __shared__ float s_red[ETHREADS / 32];

    const int tid = threadIdx.x;
    const int row = blockIdx.x * ETHREADS + tid;
    const int bidx = g_idx[row];

    float ls = 0.f;
    const float4* xp = (const float4*)(x  + (size_t)row  * DIMS);
    const float4* yp = (const float4*)(y  + (size_t)row  * DIMS);
    const float4* ep = (const float4*)(cb + (size_t)bidx * DIMS);
    float4*       op = (float4*)(out + (size_t)row * DIMS);

    #pragma unroll
    for (int i = 0; i < DIMS / 4; i++) {
        float4 xv = xp[i];
        float4 yv = yp[i];
        float4 e  = ep[i];

        float d;
        d = e.x - xv.x; ls += d * d;  d = e.x - yv.x; ls += d * d;
        d = e.y - xv.y; ls += d * d;  d = e.y - yv.y; ls += d * d;
        d = e.z - xv.z; ls += d * d;  d = e.z - yv.z; ls += d * d;
        d = e.w - xv.w; ls += d * d;  d = e.w - yv.w; ls += d * d;

        float4 o;
        float a;
        a = xv.x + yv.x; o.x = a + (e.x - a);
        a = xv.y + yv.y; o.y = a + (e.y - a);
        a = xv.z + yv.z; o.z = a + (e.z - a);
        a = xv.w + yv.w; o.w = a + (e.w - a);
        op[i] = o;
    }

    #pragma unroll
    for (int off = 16; off > 0; off >>= 1)
        ls += __shfl_xor_sync(0xffffffffu, ls, off);
    if ((tid & 31) == 0) s_red[tid >> 5] = ls;
    __syncthreads();
    if (tid == 0) {
        float s = 0.f;
        #pragma unroll
        for (int w = 0; w < ETHREADS / 32; w++) s += s_red[w];
        g_bsum[blockIdx.x] = s;
    }
}

// ---------- deterministic final loss ----------
__global__ void vq_fin(float* __restrict__ out) {
    if (threadIdx.x == 0 && blockIdx.x == 0) {
        double acc = 0.0;
        for (int i = 0; i < EBLOCKS; i++) acc += (double)g_bsum[i];
        double loss = 1.25 * acc / (double)((size_t)N_ROWS * DIMS);
        out[(size_t)N_ROWS * DIMS] = (float)loss;
    }
}

extern "C" void kernel_launch(void* const* d_in, const int* in_sizes, int n_in,
                              void* d_out, int out_size) {
    const float* x  = (const float*)d_in[0];
    const float* y  = (const float*)d_in[1];
    const float* cb = (const float*)d_in[2];
    float* out = (float*)d_out;

    static int smem_set = 0;
    if (!smem_set) {
        cudaFuncSetAttribute(vq_gemm, cudaFuncAttributeMaxDynamicSharedMemorySize, SMEM_TOTAL);
        smem_set = 1;
    }

    vq_init<<<(KENT + 255) / 256, 256>>>(cb);
    vq_prep_cb<<<(KENT * DIMS / 4 + 255) / 256, 256>>>(cb);
    vq_gemm<<<GBLOCKS, 256, SMEM_TOTAL>>>(x);
    vq_mid<<<512, 256>>>(x, cb);
    vq_exact<<<256, 256>>>(x, cb);
    vq_epi<<<EBLOCKS, ETHREADS>>>(x, y, cb, out);
    vq_fin<<<1, 1>>>(out);
}

// round 9
// speedup vs baseline: 1.8525x; 1.8525x over previous
#include <cuda_runtime.h>
#include <cuda_fp16.h>
#include <cstdint>
#include <cfloat>

// Problem constants
#define N_ROWS  131072
#define DIMS    64
#define KENT    4096
#define GM      128            // rows per CTA
#define GN      64             // codes per chunk
#define NCHUNK  (KENT / GN)    // 64
#define GBLOCKS (N_ROWS / GM)  // 1024
#define ETHREADS 256
#define EBLOCKS (N_ROWS / ETHREADS)
#define TAU1    0.03f          // fp16 single-pass gemm margin -> tier-1
#define TAU2    1e-3f          // fp16 3-term gemm margin -> tier-2 (bit-exact)
#define GK2     192            // tier-1 K: [xh|xh|xl] . [eh|el|eh]

// gemm1 smem: padded row stride 144B
#define SROW1   144
#define B1_OFF  (GM * SROW1)              // 18432
#define B1_BYTES (GN * SROW1)             // 9216
#define EN1_OFF (B1_OFF + 2 * B1_BYTES)
#define SMEM1_TOTAL (EN1_OFF + 2 * 256)   // 37376

// gemm2 smem: padded row stride 400B (K=192)
#define SROW2   400
#define B2_OFF  (GM * SROW2)              // 51200
#define B2_BYTES (GN * SROW2)             // 25600
#define EN2_OFF (B2_OFF + 2 * B2_BYTES)
#define SMEM2_TOTAL (EN2_OFF + 2 * 256)   // 102912

// Scratch
__device__ __half g_bh[(size_t)KENT * DIMS];    // fp16 codebook (tier-0), 512 KB
__device__ __half g_b3[(size_t)KENT * GK2];     // fp16 [eh|el|eh] (tier-1), 1.5 MB
__device__ float g_enorm[KENT];
__device__ float g_en2[KENT];
__device__ float g_bsum[EBLOCKS];
__device__ int   g_idx[N_ROWS];
__device__ int   g_list[N_ROWS];
__device__ int   g_list2[N_ROWS];
__device__ int   g_cnt, g_cnt2;

// ---------------- helpers (plain sm_103-safe) ----------------
__device__ __forceinline__ uint32_t smem_u32(const void* p) {
    uint32_t a;
    asm("{ .reg .u64 t; cvta.to.shared.u64 t, %1; cvt.u32.u64 %0, t; }" : "=r"(a) : "l"(p));
    return a;
}
#define CP_ASYNC16(dst, src) \
    asm volatile("cp.async.cg.shared.global [%0], [%1], 16;" :: "r"(dst), "l"(src))
#define CP_COMMIT() asm volatile("cp.async.commit_group;" ::: "memory")
#define CP_WAIT(n)  asm volatile("cp.async.wait_group %0;" :: "n"(n) : "memory")

#define LDSM4(r0, r1, r2, r3, a) \
    asm volatile("ldmatrix.sync.aligned.m8n8.x4.shared.b16 {%0,%1,%2,%3}, [%4];" \
        : "=r"(r0), "=r"(r1), "=r"(r2), "=r"(r3) : "r"(a))

#define MMA16816(d, a, b0_, b1_) \
    asm volatile("mma.sync.aligned.m16n8k16.row.col.f32.f16.f16.f32 " \
        "{%0,%1,%2,%3}, {%4,%5,%6,%7}, {%8,%9}, {%0,%1,%2,%3};" \
        : "+f"((d)[0]), "+f"((d)[1]), "+f"((d)[2]), "+f"((d)[3]) \
        : "r"((a)[0]), "r"((a)[1]), "r"((a)[2]), "r"((a)[3]), "r"(b0_), "r"(b1_))

__device__ __forceinline__ void upd(float& b, float& b2, int& id, float g, int c) {
    if (g > b) { b2 = b; b = g; id = c; }
    else if (g > b2) { b2 = g; }
}

// ---------- kernel 0: codebook norms (fp64->fp32), -en/2 table, counter resets ----------
__global__ void vq_init(const float* __restrict__ cb) {
    int k = blockIdx.x * blockDim.x + threadIdx.x;
    if (k == 0) { g_cnt = 0; g_cnt2 = 0; }
    if (k < KENT) {
        const float4* p = (const float4*)(cb + (size_t)k * DIMS);
        double s = 0.0;
        #pragma unroll
        for (int i = 0; i < DIMS / 4; i++) {
            float4 v = p[i];
            s += (double)v.x * v.x + (double)v.y * v.y
               + (double)v.z * v.z + (double)v.w * v.w;
        }
        g_enorm[k] = (float)s;
        g_en2[k]   = (float)(-0.5 * s);
    }
}

// ---------- prep: cb -> fp16 (tier-0) ----------
__global__ void vq_prep_cb(const float* __restrict__ cb) {
    int i = blockIdx.x * blockDim.x + threadIdx.x;
    if (i < KENT * DIMS / 4) {
        float4 v = ((const float4*)cb)[i];
        __half2* o = (__half2*)(g_bh + (size_t)i * 4);
        o[0] = __floats2half2_rn(v.x, v.y);
        o[1] = __floats2half2_rn(v.z, v.w);
    }
}

// ---------- prep: cb -> fp16 split [eh | el | eh] (tier-1) ----------
__global__ void vq_prep_cb3(const float* __restrict__ cb) {
    int k = blockIdx.x * blockDim.x + threadIdx.x;
    if (k >= KENT) return;
    const float* e = cb + (size_t)k * DIMS;
    __half* b = g_b3 + (size_t)k * GK2;
    #pragma unroll
    for (int d = 0; d < DIMS; d++) {
        float v = e[d];
        __half h = __float2half_rn(v);
        float lo = v - __half2float(h);
        b[d]       = h;
        b[64 + d]  = __float2half_rn(lo);
        b[128 + d] = h;
    }
}

// ---------- tier 0: single-pass fp16 HMMA GEMM + fused per-row argmax ----------
__global__ __launch_bounds__(256, 2)
void vq_gemm1(const float* __restrict__ x) {
    extern __shared__ char dsm[];
    const int tid  = threadIdx.x;
    const int wid  = tid >> 5;
    const int lane = tid & 31;
    const uint32_t S = smem_u32(dsm);

    {   // build A tile (fp16) in smem
        const int rbase = blockIdx.x * GM;
        for (int idx = tid; idx < GM * DIMS; idx += 256) {
            int r = idx >> 6, d = idx & 63;
            float v = x[(size_t)(rbase + r) * DIMS + d];
            *(__half*)(dsm + r * SROW1 + 2 * d) = __float2half_rn(v);
        }
    }
    {   // prologue: chunk 0 B + en2
        const char* Bg = (const char*)g_bh;
        for (int c = tid; c < GN * 8; c += 256) {
            int rowb = c >> 3, seg = c & 7;
            CP_ASYNC16(S + B1_OFF + rowb * SROW1 + seg * 16, Bg + rowb * 128 + seg * 16);
        }
        if (tid < 16) CP_ASYNC16(S + EN1_OFF + tid * 16, (const char*)g_en2 + tid * 16);
        CP_COMMIT();
        CP_WAIT(0);
    }
    __syncthreads();

    uint32_t af[4][4];
    {
        uint32_t a_base = S + (uint32_t)(wid * 16 + (lane & 15)) * SROW1 + (uint32_t)(lane >> 4) * 16;
        #pragma unroll
        for (int k = 0; k < 4; k++)
            LDSM4(af[k][0], af[k][1], af[k][2], af[k][3], a_base + k * 32);
    }

    const uint32_t n_part = (lane & 7) + ((lane >> 4) & 1) * 8;
    const uint32_t koff_b = ((lane >> 3) & 1) * 16;

    float bestA = -FLT_MAX, best2A = -FLT_MAX;
    float bestB = -FLT_MAX, best2B = -FLT_MAX;
    int   idxA = 0, idxB = 0;

    for (int i = 0; i < NCHUNK; i++) {
        const int buf = i & 1;
        if (i + 1 < NCHUNK) {
            const char* Bg = (const char*)(g_bh + (size_t)(i + 1) * GN * DIMS);
            uint32_t Bs = S + B1_OFF + (buf ^ 1) * B1_BYTES;
            for (int c = tid; c < GN * 8; c += 256) {
                int rowb = c >> 3, seg = c & 7;
                CP_ASYNC16(Bs + rowb * SROW1 + seg * 16, Bg + rowb * 128 + seg * 16);
            }
            if (tid < 16)
                CP_ASYNC16(S + EN1_OFF + (buf ^ 1) * 256 + tid * 16,
                           (const char*)(g_en2 + (i + 1) * GN) + tid * 16);
            CP_COMMIT();
            CP_WAIT(1);
        } else {
            CP_WAIT(0);
        }
        __syncthreads();

        float d[8][4];
        #pragma unroll
        for (int t = 0; t < 8; t++)
            #pragma unroll
            for (int q = 0; q < 4; q++) d[t][q] = 0.0f;

        const uint32_t Bs = S + B1_OFF + buf * B1_BYTES;
        #pragma unroll
        for (int k = 0; k < 4; k++) {
            #pragma unroll
            for (int jp = 0; jp < 4; jp++) {
                uint32_t b0, b1, b2, b3;
                LDSM4(b0, b1, b2, b3, Bs + (16 * jp + n_part) * SROW1 + k * 32 + koff_b);
                MMA16816(d[2 * jp],     af[k], b0, b1);
                MMA16816(d[2 * jp + 1], af[k], b2, b3);
            }
        }

        const float* en2s = (const float*)(dsm + EN1_OFF + buf * 256);
        const int c_base = i * GN + (lane & 3) * 2;
        #pragma unroll
        for (int t = 0; t < 8; t++) {
            int col0 = t * 8 + (lane & 3) * 2;
            float e0 = en2s[col0], e1 = en2s[col0 + 1];
            int c0 = c_base + t * 8;
            upd(bestA, best2A, idxA, d[t][0] + e0, c0);
            upd(bestA, best2A, idxA, d[t][1] + e1, c0 + 1);
            upd(bestB, best2B, idxB, d[t][2] + e0, c0);
            upd(bestB, best2B, idxB, d[t][3] + e1, c0 + 1);
        }
        __syncthreads();
    }

    #pragma unroll
    for (int s = 1; s <= 2; s <<= 1) {
        float ob  = __shfl_xor_sync(0xffffffffu, bestA,  s);
        float ob2 = __shfl_xor_sync(0xffffffffu, best2A, s);
        int   oi  = __shfl_xor_sync(0xffffffffu, idxA,   s);
        if (ob > bestA) { best2A = fmaxf(bestA, ob2); bestA = ob; idxA = oi; }
        else            { best2A = fmaxf(best2A, ob); }
        ob  = __shfl_xor_sync(0xffffffffu, bestB,  s);
        ob2 = __shfl_xor_sync(0xffffffffu, best2B, s);
        oi  = __shfl_xor_sync(0xffffffffu, idxB,   s);
        if (ob > bestB) { best2B = fmaxf(bestB, ob2); bestB = ob; idxB = oi; }
        else            { best2B = fmaxf(best2B, ob); }
    }

    if ((lane & 3) == 0) {
        const int q  = lane >> 2;
        const int mA = blockIdx.x * GM + wid * 16 + q;
        const int mB = mA + 8;
        g_idx[mA] = idxA;
        g_idx[mB] = idxB;
        if (2.0f * (bestA - best2A) < TAU1) { int s = atomicAdd(&g_cnt, 1); g_list[s] = mA; }
        if (2.0f * (bestB - best2B) < TAU1) { int s = atomicAdd(&g_cnt, 1); g_list[s] = mB; }
    }
}

// ---------- tier 1: gathered fp16 3-term GEMM rescore of flagged rows ----------
// g = xh.eh + xh.el + xl.eh - ||e||^2/2 ; sigma ~ 1e-5 ; margin < TAU2 -> tier 2
__global__ __launch_bounds__(256, 2)
void vq_gemm2(const float* __restrict__ x) {
    const int cnt  = g_cnt;
    const int base = blockIdx.x * GM;
    if (base >= cnt) return;

    extern __shared__ char dsm[];
    const int tid  = threadIdx.x;
    const int wid  = tid >> 5;
    const int lane = tid & 31;
    const uint32_t S = smem_u32(dsm);

    {   // gather + split A tile: [xh | xh | xl]
        for (int idx = tid; idx < GM * DIMS; idx += 256) {
            int r = idx >> 6, d = idx & 63;
            int li = base + r;
            if (li >= cnt) li = cnt - 1;           // clamp (duplicate work, benign)
            int row = g_list[li];
            float v = x[(size_t)row * DIMS + d];
            __half h = __float2half_rn(v);
            __half l = __float2half_rn(v - __half2float(h));
            char* ar = dsm + r * SROW2;
            *(__half*)(ar + 2 * d)       = h;
            *(__half*)(ar + 128 + 2 * d) = h;
            *(__half*)(ar + 256 + 2 * d) = l;
        }
    }
    {   // prologue: chunk 0 B + en2
        const char* Bg = (const char*)g_b3;
        for (int c = tid; c < GN * 24; c += 256) {
            int rowb = c / 24, seg = c % 24;
            CP_ASYNC16(S + B2_OFF + rowb * SROW2 + seg * 16, Bg + rowb * (GK2 * 2) + seg * 16);
        }
        if (tid < 16) CP_ASYNC16(S + EN2_OFF + tid * 16, (const char*)g_en2 + tid * 16);
        CP_COMMIT();
        CP_WAIT(0);
    }
    __syncthreads();

    uint32_t af[12][4];
    {
        uint32_t a_base = S + (uint32_t)(wid * 16 + (lane & 15)) * SROW2 + (uint32_t)(lane >> 4) * 16;
        #pragma unroll
        for (int k = 0; k < 12; k++)
            LDSM4(af[k][0], af[k][1], af[k][2], af[k][3], a_base + k * 32);
    }

    const uint32_t n_part = (lane & 7) + ((lane >> 4) & 1) * 8;
    const uint32_t koff_b = ((lane >> 3) & 1) * 16;

    float bestA = -FLT_MAX, best2A = -FLT_MAX;
    float bestB = -FLT_MAX, best2B = -FLT_MAX;
    int   idxA = 0, idxB = 0;

    for (int i = 0; i < NCHUNK; i++) {
        const int buf = i & 1;
        if (i + 1 < NCHUNK) {
            const char* Bg = (const char*)(g_b3 + (size_t)(i + 1) * GN * GK2);
            uint32_t Bs = S + B2_OFF + (buf ^ 1) * B2_BYTES;
            for (int c = tid; c < GN * 24; c += 256) {
                int rowb = c / 24, seg = c % 24;
                CP_ASYNC16(Bs + rowb * SROW2 + seg * 16, Bg + rowb * (GK2 * 2) + seg * 16);
            }
            if (tid < 16)
                CP_ASYNC16(S + EN2_OFF + (buf ^ 1) * 256 + tid * 16,
                           (const char*)(g_en2 + (i + 1) * GN) + tid * 16);
            CP_COMMIT();
            CP_WAIT(1);
        } else {
            CP_WAIT(0);
        }
        __syncthreads();

        float d[8][4];
        #pragma unroll
        for (int t = 0; t < 8; t++)
            #pragma unroll
            for (int q = 0; q < 4; q++) d[t][q] = 0.0f;

        const uint32_t Bs = S + B2_OFF + buf * B2_BYTES;
        #pragma unroll
        for (int k = 0; k < 12; k++) {
            #pragma unroll
            for (int jp = 0; jp < 4; jp++) {
                uint32_t b0, b1, b2, b3;
                LDSM4(b0, b1, b2, b3, Bs + (16 * jp + n_part) * SROW2 + k * 32 + koff_b);
                MMA16816(d[2 * jp],     af[k], b0, b1);
                MMA16816(d[2 * jp + 1], af[k], b2, b3);
            }
        }

        const float* en2s = (const float*)(dsm + EN2_OFF + buf * 256);
        const int c_base = i * GN + (lane & 3) * 2;
        #pragma unroll
        for (int t = 0; t < 8; t++) {
            int col0 = t * 8 + (lane & 3) * 2;
            float e0 = en2s[col0], e1 = en2s[col0 + 1];
            int c0 = c_base + t * 8;
            upd(bestA, best2A, idxA, d[t][0] + e0, c0);
            upd(bestA, best2A, idxA, d[t][1] + e1, c0 + 1);
            upd(bestB, best2B, idxB, d[t][2] + e0, c0);
            upd(bestB, best2B, idxB, d[t][3] + e1, c0 + 1);
        }
        __syncthreads();
    }

    #pragma unroll
    for (int s = 1; s <= 2; s <<= 1) {
        float ob  = __shfl_xor_sync(0xffffffffu, bestA,  s);
        float ob2 = __shfl_xor_sync(0xffffffffu, best2A, s);
        int   oi  = __shfl_xor_sync(0xffffffffu, idxA,   s);
        if (ob > bestA) { best2A = fmaxf(bestA, ob2); bestA = ob; idxA = oi; }
        else            { best2A = fmaxf(best2A, ob); }
        ob  = __shfl_xor_sync(0xffffffffu, bestB,  s);
        ob2 = __shfl_xor_sync(0xffffffffu, best2B, s);
        oi  = __shfl_xor_sync(0xffffffffu, idxB,   s);
        if (ob > bestB) { best2B = fmaxf(bestB, ob2); bestB = ob; idxB = oi; }
        else            { best2B = fmaxf(best2B, ob); }
    }

    if ((lane & 3) == 0) {
        const int q  = lane >> 2;
        const int liA = base + wid * 16 + q;
        const int liB = liA + 8;
        if (liA < cnt) {
            const int row = g_list[liA];
            g_idx[row] = idxA;
            if (2.0f * (bestA - best2A) < TAU2) { int s = atomicAdd(&g_cnt2, 1); g_list2[s] = row; }
        }
        if (liB < cnt) {
            const int row = g_list[liB];
            g_idx[row] = idxB;
            if (2.0f * (bestB - best2B) < TAU2) { int s = atomicAdd(&g_cnt2, 1); g_list2[s] = row; }
        }
    }
}

// ---------- tier 2: bit-exact reference-emulating re-scan, warp-per-row ----------
__global__ __launch_bounds__(256)
void vq_exact(const float* __restrict__ x, const float* __restrict__ cb) {
    const int lane = threadIdx.x & 31;
    const int gw   = (blockIdx.x * blockDim.x + threadIdx.x) >> 5;
    const int nw   = (gridDim.x * blockDim.x) >> 5;
    const int cnt  = g_cnt2;

    for (int i = gw; i < cnt; i += nw) {
        const int row = g_list2[i];

        float xr[DIMS];
        {
            const float4* xp = (const float4*)(x + (size_t)row * DIMS);
            #pragma unroll
            for (int j = 0; j < DIMS / 4; j++) {
                float4 v = xp[j];
                xr[4 * j] = v.x; xr[4 * j + 1] = v.y;
                xr[4 * j + 2] = v.z; xr[4 * j + 3] = v.w;
            }
        }
        double xs;
        {
            float a = __ldg(x + (size_t)row * DIMS + 2 * lane);
            float b = __ldg(x + (size_t)row * DIMS + 2 * lane + 1);
            xs = (double)a * a + (double)b * b;
            #pragma unroll
            for (int off = 16; off > 0; off >>= 1)
                xs += __shfl_xor_sync(0xffffffffu, xs, off);
        }
        const float xnorm = (float)xs;

        float best = FLT_MAX;
        int   bi   = 0x7fffffff;
        for (int k = lane; k < KENT; k += 32) {
            const float4* e4 = (const float4*)(cb + (size_t)k * DIMS);
            float acc = 0.0f;
            #pragma unroll
            for (int q = 0; q < DIMS / 4; q++) {
                float4 e = e4[q];
                acc = fmaf(xr[4 * q + 0], e.x, acc);
                acc = fmaf(xr[4 * q + 1], e.y, acc);
                acc = fmaf(xr[4 * q + 2], e.z, acc);
                acc = fmaf(xr[4 * q + 3], e.w, acc);
            }
            float t    = xnorm + __ldg(&g_enorm[k]);
            float dist = t - 2.0f * acc;
            if (dist < best) { best = dist; bi = k; }
        }
        #pragma unroll
        for (int s = 1; s < 32; s <<= 1) {
            float ob = __shfl_xor_sync(0xffffffffu, best, s);
            int   oi = __shfl_xor_sync(0xffffffffu, bi,   s);
            if (ob < best || (ob == best && oi < bi)) { best = ob; bi = oi; }
        }
        if (lane == 0) g_idx[row] = bi;
    }
}

// ---------- epilogue: gather winner, straight-through output, loss partials ----------
__global__ __launch_bounds__(ETHREADS)
void vq_epi(const float* __restrict__ x, const float* __restrict__ y,
            const float* __restrict__ cb, float* __restrict__ out) {
    __shared__ float s_red[ETHREADS / 32];

    const int tid = threadIdx.x;
    const int row = blockIdx.x * ETHREADS + tid;
    const int bidx = g_idx[row];

    float ls = 0.f;
    const float4* xp = (const float4*)(x  + (size_t)row  * DIMS);
    const float4* yp = (const float4*)(y  + (size_t)row  * DIMS);
    const float4* ep = (const float4*)(cb + (size_t)bidx * DIMS);
    float4*       op = (float4*)(out + (size_t)row * DIMS);

    #pragma unroll
    for (int i = 0; i < DIMS / 4; i++) {
        float4 xv = xp[i];
        float4 yv = yp[i];
        float4 e  = ep[i];

        float d;
        d = e.x - xv.x; ls += d * d;  d = e.x - yv.x; ls += d * d;
        d = e.y - xv.y; ls += d * d;  d = e.y - yv.y; ls += d * d;
        d = e.z - xv.z; ls += d * d;  d = e.z - yv.z; ls += d * d;
        d = e.w - xv.w; ls += d * d;  d = e.w - yv.w; ls += d * d;

        float4 o;
        float a;
        a = xv.x + yv.x; o.x = a + (e.x - a);
        a = xv.y + yv.y; o.y = a + (e.y - a);
        a = xv.z + yv.z; o.z = a + (e.z - a);
        a = xv.w + yv.w; o.w = a + (e.w - a);
        op[i] = o;
    }

    #pragma unroll
    for (int off = 16; off > 0; off >>= 1)
        ls += __shfl_xor_sync(0xffffffffu, ls, off);
    if ((tid & 31) == 0) s_red[tid >> 5] = ls;
    __syncthreads();
    if (tid == 0) {
        float s = 0.f;
        #pragma unroll
        for (int w = 0; w < ETHREADS / 32; w++) s += s_red[w];
        g_bsum[blockIdx.x] = s;
    }
}

// ---------- deterministic final loss ----------
__global__ void vq_fin(float* __restrict__ out) {
    if (threadIdx.x == 0 && blockIdx.x == 0) {
        double acc = 0.0;
        for (int i = 0; i < EBLOCKS; i++) acc += (double)g_bsum[i];
        double loss = 1.25 * acc / (double)((size_t)N_ROWS * DIMS);
        out[(size_t)N_ROWS * DIMS] = (float)loss;
    }
}

extern "C" void kernel_launch(void* const* d_in, const int* in_sizes, int n_in,
                              void* d_out, int out_size) {
    const float* x  = (const float*)d_in[0];
    const float* y  = (const float*)d_in[1];
    const float* cb = (const float*)d_in[2];
    float* out = (float*)d_out;

    static int smem_set = 0;
    if (!smem_set) {
        cudaFuncSetAttribute(vq_gemm1, cudaFuncAttributeMaxDynamicSharedMemorySize, SMEM1_TOTAL);
        cudaFuncSetAttribute(vq_gemm2, cudaFuncAttributeMaxDynamicSharedMemorySize, SMEM2_TOTAL);
        smem_set = 1;
    }

    vq_init<<<(KENT + 255) / 256, 256>>>(cb);
    vq_prep_cb<<<(KENT * DIMS / 4 + 255) / 256, 256>>>(cb);
    vq_prep_cb3<<<(KENT + 255) / 256, 256>>>(cb);
    vq_gemm1<<<GBLOCKS, 256, SMEM1_TOTAL>>>(x);
    vq_gemm2<<<GBLOCKS, 256, SMEM2_TOTAL>>>(x);     // early-exits past g_cnt
    vq_exact<<<256, 256>>>(x, cb);
    vq_epi<<<EBLOCKS, ETHREADS>>>(x, y, cb, out);
    vq_fin<<<1, 1>>>(out);
}

// round 10
// speedup vs baseline: 2.0767x; 1.1210x over previous
#include <cuda_runtime.h>
#include <cuda_fp16.h>
#include <cstdint>
#include <cfloat>

// Problem constants
#define N_ROWS  131072
#define DIMS    64
#define KENT    4096
#define GM      128            // rows per CTA
#define GN      64             // codes per chunk
#define NCHUNK  (KENT / GN)    // 64
#define GBLOCKS (N_ROWS / GM)  // 1024
#define NSPLIT  4              // tier-1 N splits
#define CHUNKS_PER_SPLIT (NCHUNK / NSPLIT)   // 16
#define ETHREADS 256
#define EBLOCKS (N_ROWS / ETHREADS)
#define TAU1    0.03f          // fp16 single-pass gemm margin -> tier-1
#define TAU2    1e-3f          // fp16 3-term gemm margin -> tier-2 (bit-exact)
#define GK2     192            // tier-1 K: [xh|xh|xl] . [eh|el|eh]

// gemm1 smem
#define SROW1   144
#define B1_OFF  (GM * SROW1)
#define B1_BYTES (GN * SROW1)
#define EN1_OFF (B1_OFF + 2 * B1_BYTES)
#define SMEM1_TOTAL (EN1_OFF + 2 * 256)   // 37376

// gemm2 smem
#define SROW2   400
#define B2_OFF  (GM * SROW2)
#define B2_BYTES (GN * SROW2)
#define EN2_OFF (B2_OFF + 2 * B2_BYTES)
#define SMEM2_TOTAL (EN2_OFF + 2 * 256)   // 102912

// Scratch
__device__ __half g_bh[(size_t)KENT * DIMS];
__device__ __half g_b3[(size_t)KENT * GK2];
__device__ float g_enorm[KENT];
__device__ float g_en2[KENT];
__device__ float g_bsum[EBLOCKS];
__device__ int   g_idx[N_ROWS];
__device__ int   g_list[N_ROWS];
__device__ int   g_list2[N_ROWS];
__device__ int   g_cnt, g_cnt2;
// tier-1 per-(listpos, split) partial top-2
__device__ float g_pb [(size_t)N_ROWS * NSPLIT];
__device__ float g_pb2[(size_t)N_ROWS * NSPLIT];
__device__ int   g_pi [(size_t)N_ROWS * NSPLIT];

// ---------------- helpers ----------------
__device__ __forceinline__ uint32_t smem_u32(const void* p) {
    uint32_t a;
    asm("{ .reg .u64 t; cvta.to.shared.u64 t, %1; cvt.u32.u64 %0, t; }" : "=r"(a) : "l"(p));
    return a;
}
#define CP_ASYNC16(dst, src) \
    asm volatile("cp.async.cg.shared.global [%0], [%1], 16;" :: "r"(dst), "l"(src))
#define CP_COMMIT() asm volatile("cp.async.commit_group;" ::: "memory")
#define CP_WAIT(n)  asm volatile("cp.async.wait_group %0;" :: "n"(n) : "memory")

#define LDSM4(r0, r1, r2, r3, a) \
    asm volatile("ldmatrix.sync.aligned.m8n8.x4.shared.b16 {%0,%1,%2,%3}, [%4];" \
        : "=r"(r0), "=r"(r1), "=r"(r2), "=r"(r3) : "r"(a))

#define MMA16816(d, a, b0_, b1_) \
    asm volatile("mma.sync.aligned.m16n8k16.row.col.f32.f16.f16.f32 " \
        "{%0,%1,%2,%3}, {%4,%5,%6,%7}, {%8,%9}, {%0,%1,%2,%3};" \
        : "+f"((d)[0]), "+f"((d)[1]), "+f"((d)[2]), "+f"((d)[3]) \
        : "r"((a)[0]), "r"((a)[1]), "r"((a)[2]), "r"((a)[3]), "r"(b0_), "r"(b1_))

__device__ __forceinline__ void upd(float& b, float& b2, int& id, float g, int c) {
    if (g > b) { b2 = b; b = g; id = c; }
    else if (g > b2) { b2 = g; }
}

// ---------- kernel 0 ----------
__global__ void vq_init(const float* __restrict__ cb) {
    int k = blockIdx.x * blockDim.x + threadIdx.x;
    if (k == 0) { g_cnt = 0; g_cnt2 = 0; }
    if (k < KENT) {
        const float4* p = (const float4*)(cb + (size_t)k * DIMS);
        double s = 0.0;
        #pragma unroll
        for (int i = 0; i < DIMS / 4; i++) {
            float4 v = p[i];
            s += (double)v.x * v.x + (double)v.y * v.y
               + (double)v.z * v.z + (double)v.w * v.w;
        }
        g_enorm[k] = (float)s;
        g_en2[k]   = (float)(-0.5 * s);
    }
}

__global__ void vq_prep_cb(const float* __restrict__ cb) {
    int i = blockIdx.x * blockDim.x + threadIdx.x;
    if (i < KENT * DIMS / 4) {
        float4 v = ((const float4*)cb)[i];
        __half2* o = (__half2*)(g_bh + (size_t)i * 4);
        o[0] = __floats2half2_rn(v.x, v.y);
        o[1] = __floats2half2_rn(v.z, v.w);
    }
}

__global__ void vq_prep_cb3(const float* __restrict__ cb) {
    int k = blockIdx.x * blockDim.x + threadIdx.x;
    if (k >= KENT) return;
    const float* e = cb + (size_t)k * DIMS;
    __half* b = g_b3 + (size_t)k * GK2;
    #pragma unroll
    for (int d = 0; d < DIMS; d++) {
        float v = e[d];
        __half h = __float2half_rn(v);
        float lo = v - __half2float(h);
        b[d]       = h;
        b[64 + d]  = __float2half_rn(lo);
        b[128 + d] = h;
    }
}

// ---------- tier 0: fp16 HMMA GEMM + lazy top-2 argmax ----------
__global__ __launch_bounds__(256, 2)
void vq_gemm1(const float* __restrict__ x) {
    extern __shared__ char dsm[];
    const int tid  = threadIdx.x;
    const int wid  = tid >> 5;
    const int lane = tid & 31;
    const uint32_t S = smem_u32(dsm);

    {
        const int rbase = blockIdx.x * GM;
        for (int idx = tid; idx < GM * DIMS; idx += 256) {
            int r = idx >> 6, d = idx & 63;
            float v = x[(size_t)(rbase + r) * DIMS + d];
            *(__half*)(dsm + r * SROW1 + 2 * d) = __float2half_rn(v);
        }
    }
    {
        const char* Bg = (const char*)g_bh;
        for (int c = tid; c < GN * 8; c += 256) {
            int rowb = c >> 3, seg = c & 7;
            CP_ASYNC16(S + B1_OFF + rowb * SROW1 + seg * 16, Bg + rowb * 128 + seg * 16);
        }
        if (tid < 16) CP_ASYNC16(S + EN1_OFF + tid * 16, (const char*)g_en2 + tid * 16);
        CP_COMMIT();
        CP_WAIT(0);
    }
    __syncthreads();

    uint32_t af[4][4];
    {
        uint32_t a_base = S + (uint32_t)(wid * 16 + (lane & 15)) * SROW1 + (uint32_t)(lane >> 4) * 16;
        #pragma unroll
        for (int k = 0; k < 4; k++)
            LDSM4(af[k][0], af[k][1], af[k][2], af[k][3], a_base + k * 32);
    }

    const uint32_t n_part = (lane & 7) + ((lane >> 4) & 1) * 8;
    const uint32_t koff_b = ((lane >> 3) & 1) * 16;
    const int pidx = lane & 3;

    float bestA = -FLT_MAX, best2A = -FLT_MAX;
    float bestB = -FLT_MAX, best2B = -FLT_MAX;
    int   idxA = 0, idxB = 0;

    for (int i = 0; i < NCHUNK; i++) {
        const int buf = i & 1;
        if (i + 1 < NCHUNK) {
            const char* Bg = (const char*)(g_bh + (size_t)(i + 1) * GN * DIMS);
            uint32_t Bs = S + B1_OFF + (buf ^ 1) * B1_BYTES;
            for (int c = tid; c < GN * 8; c += 256) {
                int rowb = c >> 3, seg = c & 7;
                CP_ASYNC16(Bs + rowb * SROW1 + seg * 16, Bg + rowb * 128 + seg * 16);
            }
            if (tid < 16)
                CP_ASYNC16(S + EN1_OFF + (buf ^ 1) * 256 + tid * 16,
                           (const char*)(g_en2 + (i + 1) * GN) + tid * 16);
            CP_COMMIT();
            CP_WAIT(1);
        } else {
            CP_WAIT(0);
        }
        __syncthreads();

        float d[8][4];
        #pragma unroll
        for (int t = 0; t < 8; t++)
            #pragma unroll
            for (int q = 0; q < 4; q++) d[t][q] = 0.0f;

        const uint32_t Bs = S + B1_OFF + buf * B1_BYTES;
        #pragma unroll
        for (int k = 0; k < 4; k++) {
            #pragma unroll
            for (int jp = 0; jp < 4; jp++) {
                uint32_t b0, b1, b2, b3;
                LDSM4(b0, b1, b2, b3, Bs + (16 * jp + n_part) * SROW1 + k * 32 + koff_b);
                MMA16816(d[2 * jp],     af[k], b0, b1);
                MMA16816(d[2 * jp + 1], af[k], b2, b3);
            }
        }

        // lazy top-2 epilogue
        const float2* env = (const float2*)(dsm + EN1_OFF + buf * 256);
        float mA = -FLT_MAX, mB = -FLT_MAX;
        #pragma unroll
        for (int t = 0; t < 8; t++) {
            float2 e = env[t * 4 + pidx];
            mA = fmaxf(mA, fmaxf(d[t][0] + e.x, d[t][1] + e.y));
            mB = fmaxf(mB, fmaxf(d[t][2] + e.x, d[t][3] + e.y));
        }
        const int c_base = i * GN + pidx * 2;
        if (mA > best2A) {
            #pragma unroll
            for (int t = 0; t < 8; t++) {
                float2 e = env[t * 4 + pidx];
                upd(bestA, best2A, idxA, d[t][0] + e.x, c_base + t * 8);
                upd(bestA, best2A, idxA, d[t][1] + e.y, c_base + t * 8 + 1);
            }
        }
        if (mB > best2B) {
            #pragma unroll
            for (int t = 0; t < 8; t++) {
                float2 e = env[t * 4 + pidx];
                upd(bestB, best2B, idxB, d[t][2] + e.x, c_base + t * 8);
                upd(bestB, best2B, idxB, d[t][3] + e.y, c_base + t * 8 + 1);
            }
        }
        __syncthreads();
    }

    #pragma unroll
    for (int s = 1; s <= 2; s <<= 1) {
        float ob  = __shfl_xor_sync(0xffffffffu, bestA,  s);
        float ob2 = __shfl_xor_sync(0xffffffffu, best2A, s);
        int   oi  = __shfl_xor_sync(0xffffffffu, idxA,   s);
        if (ob > bestA) { best2A = fmaxf(bestA, ob2); bestA = ob; idxA = oi; }
        else            { best2A = fmaxf(best2A, ob); }
        ob  = __shfl_xor_sync(0xffffffffu, bestB,  s);
        ob2 = __shfl_xor_sync(0xffffffffu, best2B, s);
        oi  = __shfl_xor_sync(0xffffffffu, idxB,   s);
        if (ob > bestB) { best2B = fmaxf(bestB, ob2); bestB = ob; idxB = oi; }
        else            { best2B = fmaxf(best2B, ob); }
    }

    if ((lane & 3) == 0) {
        const int q  = lane >> 2;
        const int mA = blockIdx.x * GM + wid * 16 + q;
        const int mB = mA + 8;
        g_idx[mA] = idxA;
        g_idx[mB] = idxB;
        if (2.0f * (bestA - best2A) < TAU1) { int s = atomicAdd(&g_cnt, 1); g_list[s] = mA; }
        if (2.0f * (bestB - best2B) < TAU1) { int s = atomicAdd(&g_cnt, 1); g_list[s] = mB; }
    }
}

// ---------- tier 1: gathered fp16 3-term GEMM, N-split partials ----------
__global__ __launch_bounds__(256, 2)
void vq_gemm2(const float* __restrict__ x) {
    const int cnt  = g_cnt;
    const int base = blockIdx.x * GM;
    if (base >= cnt) return;
    const int by = blockIdx.y;            // N split 0..3
    const int c0 = by * CHUNKS_PER_SPLIT; // first chunk

    extern __shared__ char dsm[];
    const int tid  = threadIdx.x;
    const int wid  = tid >> 5;
    const int lane = tid & 31;
    const uint32_t S = smem_u32(dsm);

    {   // gather + split A tile: [xh | xh | xl]
        for (int idx = tid; idx < GM * DIMS; idx += 256) {
            int r = idx >> 6, d = idx & 63;
            int li = base + r;
            if (li >= cnt) li = cnt - 1;
            int row = g_list[li];
            float v = x[(size_t)row * DIMS + d];
            __half h = __float2half_rn(v);
            __half l = __float2half_rn(v - __half2float(h));
            char* ar = dsm + r * SROW2;
            *(__half*)(ar + 2 * d)       = h;
            *(__half*)(ar + 128 + 2 * d) = h;
            *(__half*)(ar + 256 + 2 * d) = l;
        }
    }
    {
        const char* Bg = (const char*)(g_b3 + (size_t)c0 * GN * GK2);
        for (int c = tid; c < GN * 24; c += 256) {
            int rowb = c / 24, seg = c % 24;
            CP_ASYNC16(S + B2_OFF + rowb * SROW2 + seg * 16, Bg + rowb * (GK2 * 2) + seg * 16);
        }
        if (tid < 16) CP_ASYNC16(S + EN2_OFF + tid * 16, (const char*)(g_en2 + c0 * GN) + tid * 16);
        CP_COMMIT();
        CP_WAIT(0);
    }
    __syncthreads();

    uint32_t af[12][4];
    {
        uint32_t a_base = S + (uint32_t)(wid * 16 + (lane & 15)) * SROW2 + (uint32_t)(lane >> 4) * 16;
        #pragma unroll
        for (int k = 0; k < 12; k++)
            LDSM4(af[k][0], af[k][1], af[k][2], af[k][3], a_base + k * 32);
    }

    const uint32_t n_part = (lane & 7) + ((lane >> 4) & 1) * 8;
    const uint32_t koff_b = ((lane >> 3) & 1) * 16;
    const int pidx = lane & 3;

    float bestA = -FLT_MAX, best2A = -FLT_MAX;
    float bestB = -FLT_MAX, best2B = -FLT_MAX;
    int   idxA = 0, idxB = 0;

    for (int ii = 0; ii < CHUNKS_PER_SPLIT; ii++) {
        const int i = c0 + ii;
        const int buf = ii & 1;
        if (ii + 1 < CHUNKS_PER_SPLIT) {
            const char* Bg = (const char*)(g_b3 + (size_t)(i + 1) * GN * GK2);
            uint32_t Bs = S + B2_OFF + (buf ^ 1) * B2_BYTES;
            for (int c = tid; c < GN * 24; c += 256) {
                int rowb = c / 24, seg = c % 24;
                CP_ASYNC16(Bs + rowb * SROW2 + seg * 16, Bg + rowb * (GK2 * 2) + seg * 16);
            }
            if (tid < 16)
                CP_ASYNC16(S + EN2_OFF + (buf ^ 1) * 256 + tid * 16,
                           (const char*)(g_en2 + (i + 1) * GN) + tid * 16);
            CP_COMMIT();
            CP_WAIT(1);
        } else {
            CP_WAIT(0);
        }
        __syncthreads();

        float d[8][4];
        #pragma unroll
        for (int t = 0; t < 8; t++)
            #pragma unroll
            for (int q = 0; q < 4; q++) d[t][q] = 0.0f;

        const uint32_t Bs = S + B2_OFF + buf * B2_BYTES;
        #pragma unroll
        for (int k = 0; k < 12; k++) {
            #pragma unroll
            for (int jp = 0; jp < 4; jp++) {
                uint32_t b0, b1, b2, b3;
                LDSM4(b0, b1, b2, b3, Bs + (16 * jp + n_part) * SROW2 + k * 32 + koff_b);
                MMA16816(d[2 * jp],     af[k], b0, b1);
                MMA16816(d[2 * jp + 1], af[k], b2, b3);
            }
        }

        const float2* env = (const float2*)(dsm + EN2_OFF + buf * 256);
        float mA = -FLT_MAX, mB = -FLT_MAX;
        #pragma unroll
        for (int t = 0; t < 8; t++) {
            float2 e = env[t * 4 + pidx];
            mA = fmaxf(mA, fmaxf(d[t][0] + e.x, d[t][1] + e.y));
            mB = fmaxf(mB, fmaxf(d[t][2] + e.x, d[t][3] + e.y));
        }
        const int c_base = i * GN + pidx * 2;
        if (mA > best2A) {
            #pragma unroll
            for (int t = 0; t < 8; t++) {
                float2 e = env[t * 4 + pidx];
                upd(bestA, best2A, idxA, d[t][0] + e.x, c_base + t * 8);
                upd(bestA, best2A, idxA, d[t][1] + e.y, c_base + t * 8 + 1);
            }
        }
        if (mB > best2B) {
            #pragma unroll
            for (int t = 0; t < 8; t++) {
                float2 e = env[t * 4 + pidx];
                upd(bestB, best2B, idxB, d[t][2] + e.x, c_base + t * 8);
                upd(bestB, best2B, idxB, d[t][3] + e.y, c_base + t * 8 + 1);
            }
        }
        __syncthreads();
    }

    #pragma unroll
    for (int s = 1; s <= 2; s <<= 1) {
        float ob  = __shfl_xor_sync(0xffffffffu, bestA,  s);
        float ob2 = __shfl_xor_sync(0xffffffffu, best2A, s);
        int   oi  = __shfl_xor_sync(0xffffffffu, idxA,   s);
        if (ob > bestA) { best2A = fmaxf(bestA, ob2); bestA = ob; idxA = oi; }
        else            { best2A = fmaxf(best2A, ob); }
        ob  = __shfl_xor_sync(0xffffffffu, bestB,  s);
        ob2 = __shfl_xor_sync(0xffffffffu, best2B, s);
        oi  = __shfl_xor_sync(0xffffffffu, idxB,   s);
        if (ob > bestB) { best2B = fmaxf(bestB, ob2); bestB = ob; idxB = oi; }
        else            { best2B = fmaxf(best2B, ob); }
    }

    if ((lane & 3) == 0) {
        const int q   = lane >> 2;
        const int liA = base + wid * 16 + q;
        const int liB = liA + 8;
        if (liA < cnt) {
            g_pb [(size_t)liA * NSPLIT + by] = bestA;
            g_pb2[(size_t)liA * NSPLIT + by] = best2A;
            g_pi [(size_t)liA * NSPLIT + by] = idxA;
        }
        if (liB < cnt) {
            g_pb [(size_t)liB * NSPLIT + by] = bestB;
            g_pb2[(size_t)liB * NSPLIT + by] = best2B;
            g_pi [(size_t)liB * NSPLIT + by] = idxB;
        }
    }
}

// ---------- merge N-split partials; route marginal rows to tier 2 ----------
__global__ void vq_merge() {
    const int i = blockIdx.x * blockDim.x + threadIdx.x;
    if (i >= g_cnt) return;
    const int row = g_list[i];

    float best = -FLT_MAX, best2 = -FLT_MAX;
    int   idx  = 0;
    #pragma unroll
    for (int s = 0; s < NSPLIT; s++) {
        float b  = g_pb [(size_t)i * NSPLIT + s];
        float b2 = g_pb2[(size_t)i * NSPLIT + s];
        int   id = g_pi [(size_t)i * NSPLIT + s];
        if (b > best) { best2 = fmaxf(best, b2); best = b; idx = id; }
        else          { best2 = fmaxf(best2, b); }
    }
    g_idx[row] = idx;
    if (2.0f * (best - best2) < TAU2) {
        int s = atomicAdd(&g_cnt2, 1);
        g_list2[s] = row;
    }
}

// ---------- tier 2: bit-exact reference-emulating re-scan, warp-per-row ----------
__global__ __launch_bounds__(256)
void vq_exact(const float* __restrict__ x, const float* __restrict__ cb) {
    const int lane = threadIdx.x & 31;
    const int gw   = (blockIdx.x * blockDim.x + threadIdx.x) >> 5;
    const int nw   = (gridDim.x * blockDim.x) >> 5;
    const int cnt  = g_cnt2;

    for (int i = gw; i < cnt; i += nw) {
        const int row = g_list2[i];

        float xr[DIMS];
        {
            const float4* xp = (const float4*)(x + (size_t)row * DIMS);
            #pragma unroll
            for (int j = 0; j < DIMS / 4; j++) {
                float4 v = xp[j];
                xr[4 * j] = v.x; xr[4 * j + 1] = v.y;
                xr[4 * j + 2] = v.z; xr[4 * j + 3] = v.w;
            }
        }
        double xs;
        {
            float a = __ldg(x + (size_t)row * DIMS + 2 * lane);
            float b = __ldg(x + (size_t)row * DIMS + 2 * lane + 1);
            xs = (double)a * a + (double)b * b;
            #pragma unroll
            for (int off = 16; off > 0; off >>= 1)
                xs += __shfl_xor_sync(0xffffffffu, xs, off);
        }
        const float xnorm = (float)xs;

        float best = FLT_MAX;
        int   bi   = 0x7fffffff;
        for (int k = lane; k < KENT; k += 32) {
            const float4* e4 = (const float4*)(cb + (size_t)k * DIMS);
            float acc = 0.0f;
            #pragma unroll
            for (int q = 0; q < DIMS / 4; q++) {
                float4 e = e4[q];
                acc = fmaf(xr[4 * q + 0], e.x, acc);
                acc = fmaf(xr[4 * q + 1], e.y, acc);
                acc = fmaf(xr[4 * q + 2], e.z, acc);
                acc = fmaf(xr[4 * q + 3], e.w, acc);
            }
            float t    = xnorm + __ldg(&g_enorm[k]);
            float dist = t - 2.0f * acc;
            if (dist < best) { best = dist; bi = k; }
        }
        #pragma unroll
        for (int s = 1; s < 32; s <<= 1) {
            float ob = __shfl_xor_sync(0xffffffffu, best, s);
            int   oi = __shfl_xor_sync(0xffffffffu, bi,   s);
            if (ob < best || (ob == best && oi < bi)) { best = ob; bi = oi; }
        }
        if (lane == 0) g_idx[row] = bi;
    }
}

// ---------- epilogue ----------
__global__ __launch_bounds__(ETHREADS)
void vq_epi(const float* __restrict__ x, const float* __restrict__ y,
            const float* __restrict__ cb, float* __restrict__ out) {
    __shared__ float s_red[ETHREADS / 32];

    const int tid = threadIdx.x;
    const int row = blockIdx.x * ETHREADS + tid;
    const int bidx = g_idx[row];

    float ls = 0.f;
    const float4* xp = (const float4*)(x  + (size_t)row  * DIMS);
    const float4* yp = (const float4*)(y  + (size_t)row  * DIMS);
    const float4* ep = (const float4*)(cb + (size_t)bidx * DIMS);
    float4*       op = (float4*)(out + (size_t)row * DIMS);

    #pragma unroll
    for (int i = 0; i < DIMS / 4; i++) {
        float4 xv = xp[i];
        float4 yv = yp[i];
        float4 e  = ep[i];

        float d;
        d = e.x - xv.x; ls += d * d;  d = e.x - yv.x; ls += d * d;
        d = e.y - xv.y; ls += d * d;  d = e.y - yv.y; ls += d * d;
        d = e.z - xv.z; ls += d * d;  d = e.z - yv.z; ls += d * d;
        d = e.w - xv.w; ls += d * d;  d = e.w - yv.w; ls += d * d;

        float4 o;
        float a;
        a = xv.x + yv.x; o.x = a + (e.x - a);
        a = xv.y + yv.y; o.y = a + (e.y - a);
        a = xv.z + yv.z; o.z = a + (e.z - a);
        a = xv.w + yv.w; o.w = a + (e.w - a);
        op[i] = o;
    }

    #pragma unroll
    for (int off = 16; off > 0; off >>= 1)
        ls += __shfl_xor_sync(0xffffffffu, ls, off);
    if ((tid & 31) == 0) s_red[tid >> 5] = ls;
    __syncthreads();
    if (tid == 0) {
        float s = 0.f;
        #pragma unroll
        for (int w = 0; w < ETHREADS / 32; w++) s += s_red[w];
        g_bsum[blockIdx.x] = s;
    }
}

__global__ void vq_fin(float* __restrict__ out) {
    if (threadIdx.x == 0 && blockIdx.x == 0) {
        double acc = 0.0;
        for (int i = 0; i < EBLOCKS; i++) acc += (double)g_bsum[i];
        double loss = 1.25 * acc / (double)((size_t)N_ROWS * DIMS);
        out[(size_t)N_ROWS * DIMS] = (float)loss;
    }
}

extern "C" void kernel_launch(void* const* d_in, const int* in_sizes, int n_in,
                              void* d_out, int out_size) {
    const float* x  = (const float*)d_in[0];
    const float* y  = (const float*)d_in[1];
    const float* cb = (const float*)d_in[2];
    float* out = (float*)d_out;

    static int smem_set = 0;
    if (!smem_set) {
        cudaFuncSetAttribute(vq_gemm1, cudaFuncAttributeMaxDynamicSharedMemorySize, SMEM1_TOTAL);
        cudaFuncSetAttribute(vq_gemm2, cudaFuncAttributeMaxDynamicSharedMemorySize, SMEM2_TOTAL);
        smem_set = 1;
    }

    vq_init<<<(KENT + 255) / 256, 256>>>(cb);
    vq_prep_cb<<<(KENT * DIMS / 4 + 255) / 256, 256>>>(cb);
    vq_prep_cb3<<<(KENT + 255) / 256, 256>>>(cb);
    vq_gemm1<<<GBLOCKS, 256, SMEM1_TOTAL>>>(x);
    vq_gemm2<<<dim3(GBLOCKS, NSPLIT), 256, SMEM2_TOTAL>>>(x);   // early-exits past g_cnt
    vq_merge<<<EBLOCKS, 256>>>();
    vq_exact<<<256, 256>>>(x, cb);
    vq_epi<<<EBLOCKS, ETHREADS>>>(x, y, cb, out);
    vq_fin<<<1, 1>>>(out);
}

// round 11
// speedup vs baseline: 3.0901x; 1.4880x over previous
#include <cuda_runtime.h>
#include <cuda_fp16.h>
#include <cstdint>
#include <cfloat>

// Problem constants
#define N_ROWS  131072
#define DIMS    64
#define KENT    4096
#define GM      128            // rows per CTA
#define GN      64             // codes per chunk
#define NCHUNK  (KENT / GN)    // 64
#define GBLOCKS (N_ROWS / GM)  // 1024
#define ETHREADS 256
#define EBLOCKS (N_ROWS / ETHREADS)
#define TAU1    0.03f          // fp16 dist margin -> flagged for exact candidate rescore
#define GTH     0.04f          // g-scale chunk-candidate slack (~25 sigma)

// gemm1 smem
#define SROW1   144
#define B1_OFF  (GM * SROW1)                  // 18432
#define B1_BYTES (GN * SROW1)                 // 9216
#define EN1_OFF (B1_OFF + 2 * B1_BYTES)       // 36864
#define CM_OFF  (EN1_OFF + 2 * 256)           // 37376
#define CM_STRIDE 65                          // words; conflict-free STS
#define CM_BYTES (GM * CM_STRIDE * 4)         // 33280
#define SMEM1_TOTAL (CM_OFF + CM_BYTES)       // 70656

// Scratch
__device__ __half g_bh[(size_t)KENT * DIMS];           // fp16 codebook, 512 KB
__device__ float  g_cmax[(size_t)N_ROWS * NCHUNK];     // per-row per-chunk fp16-g max, 33.5 MB
__device__ float  g_enorm[KENT];
__device__ float  g_en2[KENT];
__device__ float  g_bsum[EBLOCKS];
__device__ int    g_idx[N_ROWS];
__device__ int    g_list[N_ROWS];
__device__ int    g_cnt;

// ---------------- helpers ----------------
__device__ __forceinline__ uint32_t smem_u32(const void* p) {
    uint32_t a;
    asm("{ .reg .u64 t; cvta.to.shared.u64 t, %1; cvt.u32.u64 %0, t; }" : "=r"(a) : "l"(p));
    return a;
}
#define CP_ASYNC16(dst, src) \
    asm volatile("cp.async.cg.shared.global [%0], [%1], 16;" :: "r"(dst), "l"(src))
#define CP_COMMIT() asm volatile("cp.async.commit_group;" ::: "memory")
#define CP_WAIT(n)  asm volatile("cp.async.wait_group %0;" :: "n"(n) : "memory")

#define LDSM4(r0, r1, r2, r3, a) \
    asm volatile("ldmatrix.sync.aligned.m8n8.x4.shared.b16 {%0,%1,%2,%3}, [%4];" \
        : "=r"(r0), "=r"(r1), "=r"(r2), "=r"(r3) : "r"(a))

#define MMA16816(d, a, b0_, b1_) \
    asm volatile("mma.sync.aligned.m16n8k16.row.col.f32.f16.f16.f32 " \
        "{%0,%1,%2,%3}, {%4,%5,%6,%7}, {%8,%9}, {%0,%1,%2,%3};" \
        : "+f"((d)[0]), "+f"((d)[1]), "+f"((d)[2]), "+f"((d)[3]) \
        : "r"((a)[0]), "r"((a)[1]), "r"((a)[2]), "r"((a)[3]), "r"(b0_), "r"(b1_))

__device__ __forceinline__ void upd(float& b, float& b2, int& id, float g, int c) {
    if (g > b) { b2 = b; b = g; id = c; }
    else if (g > b2) { b2 = g; }
}

// ---------- kernel 0: norms (fp64->fp32), -en/2, counter reset ----------
__global__ void vq_init(const float* __restrict__ cb) {
    int k = blockIdx.x * blockDim.x + threadIdx.x;
    if (k == 0) g_cnt = 0;
    if (k < KENT) {
        const float4* p = (const float4*)(cb + (size_t)k * DIMS);
        double s = 0.0;
        #pragma unroll
        for (int i = 0; i < DIMS / 4; i++) {
            float4 v = p[i];
            s += (double)v.x * v.x + (double)v.y * v.y
               + (double)v.z * v.z + (double)v.w * v.w;
        }
        g_enorm[k] = (float)s;
        g_en2[k]   = (float)(-0.5 * s);
    }
}

// ---------- prep: cb -> fp16 ----------
__global__ void vq_prep_cb(const float* __restrict__ cb) {
    int i = blockIdx.x * blockDim.x + threadIdx.x;
    if (i < KENT * DIMS / 4) {
        float4 v = ((const float4*)cb)[i];
        __half2* o = (__half2*)(g_bh + (size_t)i * 4);
        o[0] = __floats2half2_rn(v.x, v.y);
        o[1] = __floats2half2_rn(v.z, v.w);
    }
}

// ---------- tier 0: fp16 HMMA GEMM + lazy top-2 argmax + chunk-max envelope ----------
__global__ __launch_bounds__(256, 2)
void vq_gemm1(const float* __restrict__ x) {
    extern __shared__ char dsm[];
    const int tid  = threadIdx.x;
    const int wid  = tid >> 5;
    const int lane = tid & 31;
    const uint32_t S = smem_u32(dsm);
    float* sm_cmax = (float*)(dsm + CM_OFF);

    {
        const int rbase = blockIdx.x * GM;
        for (int idx = tid; idx < GM * DIMS; idx += 256) {
            int r = idx >> 6, d = idx & 63;
            float v = x[(size_t)(rbase + r) * DIMS + d];
            *(__half*)(dsm + r * SROW1 + 2 * d) = __float2half_rn(v);
        }
    }
    {
        const char* Bg = (const char*)g_bh;
        for (int c = tid; c < GN * 8; c += 256) {
            int rowb = c >> 3, seg = c & 7;
            CP_ASYNC16(S + B1_OFF + rowb * SROW1 + seg * 16, Bg + rowb * 128 + seg * 16);
        }
        if (tid < 16) CP_ASYNC16(S + EN1_OFF + tid * 16, (const char*)g_en2 + tid * 16);
        CP_COMMIT();
        CP_WAIT(0);
    }
    __syncthreads();

    uint32_t af[4][4];
    {
        uint32_t a_base = S + (uint32_t)(wid * 16 + (lane & 15)) * SROW1 + (uint32_t)(lane >> 4) * 16;
        #pragma unroll
        for (int k = 0; k < 4; k++)
            LDSM4(af[k][0], af[k][1], af[k][2], af[k][3], a_base + k * 32);
    }

    const uint32_t n_part = (lane & 7) + ((lane >> 4) & 1) * 8;
    const uint32_t koff_b = ((lane >> 3) & 1) * 16;
    const int pidx = lane & 3;
    const int q    = lane >> 2;
    const int rowA_loc = wid * 16 + q;      // local row of d[..][0..1]
    const int rowB_loc = rowA_loc + 8;      // local row of d[..][2..3]

    float bestA = -FLT_MAX, best2A = -FLT_MAX;
    float bestB = -FLT_MAX, best2B = -FLT_MAX;
    int   idxA = 0, idxB = 0;

    for (int i = 0; i < NCHUNK; i++) {
        const int buf = i & 1;
        if (i + 1 < NCHUNK) {
            const char* Bg = (const char*)(g_bh + (size_t)(i + 1) * GN * DIMS);
            uint32_t Bs = S + B1_OFF + (buf ^ 1) * B1_BYTES;
            for (int c = tid; c < GN * 8; c += 256) {
                int rowb = c >> 3, seg = c & 7;
                CP_ASYNC16(Bs + rowb * SROW1 + seg * 16, Bg + rowb * 128 + seg * 16);
            }
            if (tid < 16)
                CP_ASYNC16(S + EN1_OFF + (buf ^ 1) * 256 + tid * 16,
                           (const char*)(g_en2 + (i + 1) * GN) + tid * 16);
            CP_COMMIT();
            CP_WAIT(1);
        } else {
            CP_WAIT(0);
        }
        __syncthreads();

        float d[8][4];
        #pragma unroll
        for (int t = 0; t < 8; t++)
            #pragma unroll
            for (int qq = 0; qq < 4; qq++) d[t][qq] = 0.0f;

        const uint32_t Bs = S + B1_OFF + buf * B1_BYTES;
        #pragma unroll
        for (int k = 0; k < 4; k++) {
            #pragma unroll
            for (int jp = 0; jp < 4; jp++) {
                uint32_t b0, b1, b2, b3;
                LDSM4(b0, b1, b2, b3, Bs + (16 * jp + n_part) * SROW1 + k * 32 + koff_b);
                MMA16816(d[2 * jp],     af[k], b0, b1);
                MMA16816(d[2 * jp + 1], af[k], b2, b3);
            }
        }

        // lazy top-2 epilogue + chunk-max envelope
        const float2* env = (const float2*)(dsm + EN1_OFF + buf * 256);
        float mA = -FLT_MAX, mB = -FLT_MAX;
        #pragma unroll
        for (int t = 0; t < 8; t++) {
            float2 e = env[t * 4 + pidx];
            mA = fmaxf(mA, fmaxf(d[t][0] + e.x, d[t][1] + e.y));
            mB = fmaxf(mB, fmaxf(d[t][2] + e.x, d[t][3] + e.y));
        }
        // quad-reduce: row-level chunk max
        mA = fmaxf(mA, __shfl_xor_sync(0xffffffffu, mA, 1));
        mA = fmaxf(mA, __shfl_xor_sync(0xffffffffu, mA, 2));
        mB = fmaxf(mB, __shfl_xor_sync(0xffffffffu, mB, 1));
        mB = fmaxf(mB, __shfl_xor_sync(0xffffffffu, mB, 2));
        if (pidx == 0) {
            sm_cmax[rowA_loc * CM_STRIDE + i] = mA;
            sm_cmax[rowB_loc * CM_STRIDE + i] = mB;
        }

        const int c_base = i * GN + pidx * 2;
        if (mA > best2A) {
            #pragma unroll
            for (int t = 0; t < 8; t++) {
                float2 e = env[t * 4 + pidx];
                upd(bestA, best2A, idxA, d[t][0] + e.x, c_base + t * 8);
                upd(bestA, best2A, idxA, d[t][1] + e.y, c_base + t * 8 + 1);
            }
        }
        if (mB > best2B) {
            #pragma unroll
            for (int t = 0; t < 8; t++) {
                float2 e = env[t * 4 + pidx];
                upd(bestB, best2B, idxB, d[t][2] + e.x, c_base + t * 8);
                upd(bestB, best2B, idxB, d[t][3] + e.y, c_base + t * 8 + 1);
            }
        }
        __syncthreads();
    }

    #pragma unroll
    for (int s = 1; s <= 2; s <<= 1) {
        float ob  = __shfl_xor_sync(0xffffffffu, bestA,  s);
        float ob2 = __shfl_xor_sync(0xffffffffu, best2A, s);
        int   oi  = __shfl_xor_sync(0xffffffffu, idxA,   s);
        if (ob > bestA) { best2A = fmaxf(bestA, ob2); bestA = ob; idxA = oi; }
        else            { best2A = fmaxf(best2A, ob); }
        ob  = __shfl_xor_sync(0xffffffffu, bestB,  s);
        ob2 = __shfl_xor_sync(0xffffffffu, best2B, s);
        oi  = __shfl_xor_sync(0xffffffffu, idxB,   s);
        if (ob > bestB) { best2B = fmaxf(bestB, ob2); bestB = ob; idxB = oi; }
        else            { best2B = fmaxf(best2B, ob); }
    }

    if (pidx == 0) {
        const int mA_ = blockIdx.x * GM + rowA_loc;
        const int mB_ = mA_ + 8;
        g_idx[mA_] = idxA;
        g_idx[mB_] = idxB;
        if (2.0f * (bestA - best2A) < TAU1) { int s = atomicAdd(&g_cnt, 1); g_list[s] = mA_; }
        if (2.0f * (bestB - best2B) < TAU1) { int s = atomicAdd(&g_cnt, 1); g_list[s] = mB_; }
    }

    // bulk-write chunk-max envelope (coalesced)
    {
        float* gout = g_cmax + (size_t)blockIdx.x * GM * NCHUNK;
        for (int idx = tid; idx < GM * NCHUNK; idx += 256) {
            int r = idx >> 6, i = idx & 63;
            gout[idx] = sm_cmax[r * CM_STRIDE + i];
        }
    }
}

// ---------- candidate rescore: bit-exact reference emulation over candidate chunks ----------
// For flagged rows: only chunks whose fp16-g max is within GTH of the row's best
// envelope can contain the true winner; rescore those with the validated
// reference-emulating fp32 arithmetic (sequential ascending-d fmaf; fp64 norms).
__global__ __launch_bounds__(256)
void vq_cand(const float* __restrict__ x, const float* __restrict__ cb) {
    const int lane = threadIdx.x & 31;
    const int gw   = (blockIdx.x * blockDim.x + threadIdx.x) >> 5;
    const int nw   = (gridDim.x * blockDim.x) >> 5;
    const int cnt  = g_cnt;

    for (int i = gw; i < cnt; i += nw) {
        const int row = g_list[i];

        // chunk-max envelope: 2 values per lane
        const float c0 = g_cmax[(size_t)row * NCHUNK + lane];
        const float c1 = g_cmax[(size_t)row * NCHUNK + 32 + lane];
        float bm = fmaxf(c0, c1);
        #pragma unroll
        for (int s = 16; s > 0; s >>= 1)
            bm = fmaxf(bm, __shfl_xor_sync(0xffffffffu, bm, s));
        const float thr = bm - GTH;

        // x row + fp64 xnorm (validated arithmetic)
        float xr[DIMS];
        {
            const float4* xp = (const float4*)(x + (size_t)row * DIMS);
            #pragma unroll
            for (int j = 0; j < DIMS / 4; j++) {
                float4 v = xp[j];
                xr[4 * j] = v.x; xr[4 * j + 1] = v.y;
                xr[4 * j + 2] = v.z; xr[4 * j + 3] = v.w;
            }
        }
        double xs;
        {
            float a = __ldg(x + (size_t)row * DIMS + 2 * lane);
            float b = __ldg(x + (size_t)row * DIMS + 2 * lane + 1);
            xs = (double)a * a + (double)b * b;
            #pragma unroll
            for (int off = 16; off > 0; off >>= 1)
                xs += __shfl_xor_sync(0xffffffffu, xs, off);
        }
        const float xnorm = (float)xs;

        float best = FLT_MAX;
        int   bi   = 0x7fffffff;
        for (int j = 0; j < NCHUNK; j++) {
            float cma = __shfl_sync(0xffffffffu, c0, j & 31);
            float cmb = __shfl_sync(0xffffffffu, c1, j & 31);
            float cm  = (j < 32) ? cma : cmb;
            if (cm < thr) continue;                      // uniform: all lanes agree

            const int k0 = j * GN + lane;                // lanes cover 64 codes (2 each)
            const int k1 = k0 + 32;
            const float4* e0 = (const float4*)(cb + (size_t)k0 * DIMS);
            const float4* e1 = (const float4*)(cb + (size_t)k1 * DIMS);
            float a0 = 0.0f, a1 = 0.0f;
            #pragma unroll
            for (int qd = 0; qd < DIMS / 4; qd++) {
                float4 E0 = e0[qd];
                float4 E1 = e1[qd];
                a0 = fmaf(xr[4 * qd + 0], E0.x, a0);
                a0 = fmaf(xr[4 * qd + 1], E0.y, a0);
                a0 = fmaf(xr[4 * qd + 2], E0.z, a0);
                a0 = fmaf(xr[4 * qd + 3], E0.w, a0);
                a1 = fmaf(xr[4 * qd + 0], E1.x, a1);
                a1 = fmaf(xr[4 * qd + 1], E1.y, a1);
                a1 = fmaf(xr[4 * qd + 2], E1.z, a1);
                a1 = fmaf(xr[4 * qd + 3], E1.w, a1);
            }
            float d0 = (xnorm + __ldg(&g_enorm[k0])) - 2.0f * a0;
            float d1 = (xnorm + __ldg(&g_enorm[k1])) - 2.0f * a1;
            if (d0 < best) { best = d0; bi = k0; }       // ascending within lane
            if (d1 < best) { best = d1; bi = k1; }
        }
        #pragma unroll
        for (int s = 1; s < 32; s <<= 1) {
            float ob = __shfl_xor_sync(0xffffffffu, best, s);
            int   oi = __shfl_xor_sync(0xffffffffu, bi,   s);
            if (ob < best || (ob == best && oi < bi)) { best = ob; bi = oi; }
        }
        if (lane == 0) g_idx[row] = bi;
    }
}

// ---------- epilogue: gather winner, straight-through output, loss partials ----------
__global__ __launch_bounds__(ETHREADS)
void vq_epi(const float* __restrict__ x, const float* __restrict__ y,
            const float* __restrict__ cb, float* __restrict__ out) {
    __shared__ float s_red[ETHREADS / 32];

    const int tid = threadIdx.x;
    const int row = blockIdx.x * ETHREADS + tid;
    const int bidx = g_idx[row];

    float ls = 0.f;
    const float4* xp = (const float4*)(x  + (size_t)row  * DIMS);
    const float4* yp = (const float4*)(y  + (size_t)row  * DIMS);
    const float4* ep = (const float4*)(cb + (size_t)bidx * DIMS);
    float4*       op = (float4*)(out + (size_t)row * DIMS);

    #pragma unroll
    for (int i = 0; i < DIMS / 4; i++) {
        float4 xv = xp[i];
        float4 yv = yp[i];
        float4 e  = ep[i];

        float d;
        d = e.x - xv.x; ls += d * d;  d = e.x - yv.x; ls += d * d;
        d = e.y - xv.y; ls += d * d;  d = e.y - yv.y; ls += d * d;
        d = e.z - xv.z; ls += d * d;  d = e.z - yv.z; ls += d * d;
        d = e.w - xv.w; ls += d * d;  d = e.w - yv.w; ls += d * d;

        float4 o;
        float a;
        a = xv.x + yv.x; o.x = a + (e.x - a);
        a = xv.y + yv.y; o.y = a + (e.y - a);
        a = xv.z + yv.z; o.z = a + (e.z - a);
        a = xv.w + yv.w; o.w = a + (e.w - a);
        op[i] = o;
    }

    #pragma unroll
    for (int off = 16; off > 0; off >>= 1)
        ls += __shfl_xor_sync(0xffffffffu, ls, off);
    if ((tid & 31) == 0) s_red[tid >> 5] = ls;
    __syncthreads();
    if (tid == 0) {
        float s = 0.f;
        #pragma unroll
        for (int w = 0; w < ETHREADS / 32; w++) s += s_red[w];
        g_bsum[blockIdx.x] = s;
    }
}

__global__ void vq_fin(float* __restrict__ out) {
    if (threadIdx.x == 0 && blockIdx.x == 0) {
        double acc = 0.0;
        for (int i = 0; i < EBLOCKS; i++) acc += (double)g_bsum[i];
        double loss = 1.25 * acc / (double)((size_t)N_ROWS * DIMS);
        out[(size_t)N_ROWS * DIMS] = (float)loss;
    }
}

extern "C" void kernel_launch(void* const* d_in, const int* in_sizes, int n_in,
                              void* d_out, int out_size) {
    const float* x  = (const float*)d_in[0];
    const float* y  = (const float*)d_in[1];
    const float* cb = (const float*)d_in[2];
    float* out = (float*)d_out;

    static int smem_set = 0;
    if (!smem_set) {
        cudaFuncSetAttribute(vq_gemm1, cudaFuncAttributeMaxDynamicSharedMemorySize, SMEM1_TOTAL);
        smem_set = 1;
    }

    vq_init<<<(KENT + 255) / 256, 256>>>(cb);
    vq_prep_cb<<<(KENT * DIMS / 4 + 255) / 256, 256>>>(cb);
    vq_gemm1<<<GBLOCKS, 256, SMEM1_TOTAL>>>(x);
    vq_cand<<<256, 256>>>(x, cb);
    vq_epi<<<EBLOCKS, ETHREADS>>>(x, y, cb, out);
    vq_fin<<<1, 1>>>(out);
}

// round 13
// speedup vs baseline: 3.4905x; 1.1296x over previous
#include <cuda_runtime.h>
#include <cuda_fp16.h>
#include <cstdint>
#include <cfloat>

// Problem constants
#define N_ROWS  131072
#define DIMS    64
#define KENT    4096
#define GM      128            // rows per CTA
#define GNB     256            // codes per pipeline super-chunk
#define NSUB    4              // 64-code sub-blocks per super-chunk
#define GN      64             // codes per sub-block (= cmax granularity)
#define NBIG    (KENT / GNB)   // 16
#define NCHUNK  (KENT / GN)    // 64 (cmax chunks)
#define GBLOCKS (N_ROWS / GM)  // 1024
#define ETHREADS 256
#define EBLOCKS (N_ROWS / ETHREADS)
#define TAU1    0.03f          // fp16 dist margin -> flagged for exact candidate rescore
#define GTH     0.04f          // g-scale chunk-candidate slack (~25 sigma)

// gemm1 smem
#define SROW1   144
#define A_BYTES (GM * SROW1)                  // 18432
#define B1_OFF  A_BYTES
#define B1_BYTES (GNB * SROW1)                // 36864 per buffer
#define EN1_OFF (B1_OFF + 2 * B1_BYTES)       // 92160
#define SMEM1_TOTAL (EN1_OFF + 2 * 1024)      // 94208

// Scratch
__device__ __half g_bh[(size_t)KENT * DIMS];           // fp16 codebook, 512 KB
__device__ float  g_cmax[(size_t)NCHUNK * N_ROWS];     // CHUNK-MAJOR [chunk][row], 33.5 MB
__device__ float  g_enorm[KENT];
__device__ float  g_en2[KENT];
__device__ float  g_bsum[EBLOCKS];
__device__ int    g_idx[N_ROWS];
__device__ int    g_list[N_ROWS];
__device__ int    g_cnt;

// ---------------- helpers ----------------
__device__ __forceinline__ uint32_t smem_u32(const void* p) {
    uint32_t a;
    asm("{ .reg .u64 t; cvta.to.shared.u64 t, %1; cvt.u32.u64 %0, t; }" : "=r"(a) : "l"(p));
    return a;
}
#define CP_ASYNC16(dst, src) \
    asm volatile("cp.async.cg.shared.global [%0], [%1], 16;" :: "r"(dst), "l"(src))
#define CP_COMMIT() asm volatile("cp.async.commit_group;" ::: "memory")
#define CP_WAIT(n)  asm volatile("cp.async.wait_group %0;" :: "n"(n) : "memory")

#define LDSM4(r0, r1, r2, r3, a) \
    asm volatile("ldmatrix.sync.aligned.m8n8.x4.shared.b16 {%0,%1,%2,%3}, [%4];" \
        : "=r"(r0), "=r"(r1), "=r"(r2), "=r"(r3) : "r"(a))

#define MMA16816(d, a, b0_, b1_) \
    asm volatile("mma.sync.aligned.m16n8k16.row.col.f32.f16.f16.f32 " \
        "{%0,%1,%2,%3}, {%4,%5,%6,%7}, {%8,%9}, {%0,%1,%2,%3};" \
        : "+f"((d)[0]), "+f"((d)[1]), "+f"((d)[2]), "+f"((d)[3]) \
        : "r"((a)[0]), "r"((a)[1]), "r"((a)[2]), "r"((a)[3]), "r"(b0_), "r"(b1_))

__device__ __forceinline__ void upd(float& b, float& b2, int& id, float g, int c) {
    if (g > b) { b2 = b; b = g; id = c; }
    else if (g > b2) { b2 = g; }
}

// ---------- kernel 0: norms (fp64->fp32), -en/2, counter reset ----------
__global__ void vq_init(const float* __restrict__ cb) {
    int k = blockIdx.x * blockDim.x + threadIdx.x;
    if (k == 0) g_cnt = 0;
    if (k < KENT) {
        const float4* p = (const float4*)(cb + (size_t)k * DIMS);
        double s = 0.0;
        #pragma unroll
        for (int i = 0; i < DIMS / 4; i++) {
            float4 v = p[i];
            s += (double)v.x * v.x + (double)v.y * v.y
               + (double)v.z * v.z + (double)v.w * v.w;
        }
        g_enorm[k] = (float)s;
        g_en2[k]   = (float)(-0.5 * s);
    }
}

// ---------- prep: cb -> fp16 ----------
__global__ void vq_prep_cb(const float* __restrict__ cb) {
    int i = blockIdx.x * blockDim.x + threadIdx.x;
    if (i < KENT * DIMS / 4) {
        float4 v = ((const float4*)cb)[i];
        __half2* o = (__half2*)(g_bh + (size_t)i * 4);
        o[0] = __floats2half2_rn(v.x, v.y);
        o[1] = __floats2half2_rn(v.z, v.w);
    }
}

// ---------- tier 0: fp16 HMMA GEMM, 256-code super-chunks, lazy top-2 + cmax ----------
__global__ __launch_bounds__(256, 2)
void vq_gemm1(const float* __restrict__ x) {
    extern __shared__ char dsm[];
    const int tid  = threadIdx.x;
    const int wid  = tid >> 5;
    const int lane = tid & 31;
    const uint32_t S = smem_u32(dsm);

    {
        const int rbase = blockIdx.x * GM;
        for (int idx = tid; idx < GM * DIMS; idx += 256) {
            int r = idx >> 6, d = idx & 63;
            float v = x[(size_t)(rbase + r) * DIMS + d];
            *(__half*)(dsm + r * SROW1 + 2 * d) = __float2half_rn(v);
        }
    }
    {   // prologue: super-chunk 0 B + en2
        const char* Bg = (const char*)g_bh;
        for (int c = tid; c < GNB * 8; c += 256) {
            int rowb = c >> 3, seg = c & 7;
            CP_ASYNC16(S + B1_OFF + rowb * SROW1 + seg * 16, Bg + rowb * 128 + seg * 16);
        }
        if (tid < 64) CP_ASYNC16(S + EN1_OFF + tid * 16, (const char*)g_en2 + tid * 16);
        CP_COMMIT();
        CP_WAIT(0);
    }
    __syncthreads();

    uint32_t af[4][4];
    {
        uint32_t a_base = S + (uint32_t)(wid * 16 + (lane & 15)) * SROW1 + (uint32_t)(lane >> 4) * 16;
        #pragma unroll
        for (int k = 0; k < 4; k++)
            LDSM4(af[k][0], af[k][1], af[k][2], af[k][3], a_base + k * 32);
    }

    const uint32_t n_part = (lane & 7) + ((lane >> 4) & 1) * 8;
    const uint32_t koff_b = ((lane >> 3) & 1) * 16;
    const int pidx = lane & 3;
    const int q    = lane >> 2;
    const int rowA_loc = wid * 16 + q;
    const int rowB_loc = rowA_loc + 8;
    const int rowA_g   = blockIdx.x * GM + rowA_loc;
    const int rowB_g   = rowA_g + 8;

    float bestA = -FLT_MAX, best2A = -FLT_MAX;
    float bestB = -FLT_MAX, best2B = -FLT_MAX;
    int   idxA = 0, idxB = 0;

    for (int i = 0; i < NBIG; i++) {
        const int buf = i & 1;
        if (i + 1 < NBIG) {
            const char* Bg = (const char*)(g_bh + (size_t)(i + 1) * GNB * DIMS);
            uint32_t Bs = S + B1_OFF + (buf ^ 1) * B1_BYTES;
            for (int c = tid; c < GNB * 8; c += 256) {
                int rowb = c >> 3, seg = c & 7;
                CP_ASYNC16(Bs + rowb * SROW1 + seg * 16, Bg + rowb * 128 + seg * 16);
            }
            if (tid < 64)
                CP_ASYNC16(S + EN1_OFF + (buf ^ 1) * 1024 + tid * 16,
                           (const char*)(g_en2 + (i + 1) * GNB) + tid * 16);
            CP_COMMIT();
            CP_WAIT(1);
        } else {
            CP_WAIT(0);
        }
        __syncthreads();

        // 4 sub-blocks of 64 codes back-to-back (no barriers between)
        #pragma unroll
        for (int s = 0; s < NSUB; s++) {
            float d[8][4];
            #pragma unroll
            for (int t = 0; t < 8; t++)
                #pragma unroll
                for (int qq = 0; qq < 4; qq++) d[t][qq] = 0.0f;

            const uint32_t Bs = S + B1_OFF + buf * B1_BYTES + s * (GN * SROW1);
            #pragma unroll
            for (int k = 0; k < 4; k++) {
                #pragma unroll
                for (int jp = 0; jp < 4; jp++) {
                    uint32_t b0, b1, b2, b3;
                    LDSM4(b0, b1, b2, b3, Bs + (16 * jp + n_part) * SROW1 + k * 32 + koff_b);
                    MMA16816(d[2 * jp],     af[k], b0, b1);
                    MMA16816(d[2 * jp + 1], af[k], b2, b3);
                }
            }

            // lazy top-2 epilogue + chunk-max envelope
            // en2 staging: 256 floats per buffer; sub-block s = 64 floats at s*256 BYTES
            const float2* env = (const float2*)(dsm + EN1_OFF + buf * 1024 + s * 256);
            float mA = -FLT_MAX, mB = -FLT_MAX;
            #pragma unroll
            for (int t = 0; t < 8; t++) {
                float2 e = env[t * 4 + pidx];
                mA = fmaxf(mA, fmaxf(d[t][0] + e.x, d[t][1] + e.y));
                mB = fmaxf(mB, fmaxf(d[t][2] + e.x, d[t][3] + e.y));
            }
            mA = fmaxf(mA, __shfl_xor_sync(0xffffffffu, mA, 1));
            mA = fmaxf(mA, __shfl_xor_sync(0xffffffffu, mA, 2));
            mB = fmaxf(mB, __shfl_xor_sync(0xffffffffu, mB, 1));
            mB = fmaxf(mB, __shfl_xor_sync(0xffffffffu, mB, 2));

            const int chunk = i * NSUB + s;
            if (pidx == 0) {   // chunk-major, rows consecutive within CTA -> coalesced
                g_cmax[(size_t)chunk * N_ROWS + rowA_g] = mA;
                g_cmax[(size_t)chunk * N_ROWS + rowB_g] = mB;
            }

            const int c_base = chunk * GN + pidx * 2;
            if (mA > best2A) {
                #pragma unroll
                for (int t = 0; t < 8; t++) {
                    float2 e = env[t * 4 + pidx];
                    upd(bestA, best2A, idxA, d[t][0] + e.x, c_base + t * 8);
                    upd(bestA, best2A, idxA, d[t][1] + e.y, c_base + t * 8 + 1);
                }
            }
            if (mB > best2B) {
                #pragma unroll
                for (int t = 0; t < 8; t++) {
                    float2 e = env[t * 4 + pidx];
                    upd(bestB, best2B, idxB, d[t][2] + e.x, c_base + t * 8);
                    upd(bestB, best2B, idxB, d[t][3] + e.y, c_base + t * 8 + 1);
                }
            }
        }
        __syncthreads();   // protect buf^1 before next iteration's prefetch overwrites
    }

    #pragma unroll
    for (int s = 1; s <= 2; s <<= 1) {
        float ob  = __shfl_xor_sync(0xffffffffu, bestA,  s);
        float ob2 = __shfl_xor_sync(0xffffffffu, best2A, s);
        int   oi  = __shfl_xor_sync(0xffffffffu, idxA,   s);
        if (ob > bestA) { best2A = fmaxf(bestA, ob2); bestA = ob; idxA = oi; }
        else            { best2A = fmaxf(best2A, ob); }
        ob  = __shfl_xor_sync(0xffffffffu, bestB,  s);
        ob2 = __shfl_xor_sync(0xffffffffu, best2B, s);
        oi  = __shfl_xor_sync(0xffffffffu, idxB,   s);
        if (ob > bestB) { best2B = fmaxf(bestB, ob2); bestB = ob; idxB = oi; }
        else            { best2B = fmaxf(best2B, ob); }
    }

    if (pidx == 0) {
        g_idx[rowA_g] = idxA;
        g_idx[rowB_g] = idxB;
        if (2.0f * (bestA - best2A) < TAU1) { int s = atomicAdd(&g_cnt, 1); g_list[s] = rowA_g; }
        if (2.0f * (bestB - best2B) < TAU1) { int s = atomicAdd(&g_cnt, 1); g_list[s] = rowB_g; }
    }
}

// ---------- candidate rescore: bit-exact reference emulation over candidate chunks ----------
__global__ __launch_bounds__(256)
void vq_cand(const float* __restrict__ x, const float* __restrict__ cb) {
    const int lane = threadIdx.x & 31;
    const int gw   = (blockIdx.x * blockDim.x + threadIdx.x) >> 5;
    const int nw   = (gridDim.x * blockDim.x) >> 5;
    const int cnt  = g_cnt;

    for (int i = gw; i < cnt; i += nw) {
        const int row = g_list[i];

        // chunk-max envelope (chunk-major layout): 2 values per lane
        const float c0 = g_cmax[(size_t)lane * N_ROWS + row];
        const float c1 = g_cmax[(size_t)(lane + 32) * N_ROWS + row];
        float bm = fmaxf(c0, c1);
        #pragma unroll
        for (int s = 16; s > 0; s >>= 1)
            bm = fmaxf(bm, __shfl_xor_sync(0xffffffffu, bm, s));
        const float thr = bm - GTH;

        float xr[DIMS];
        {
            const float4* xp = (const float4*)(x + (size_t)row * DIMS);
            #pragma unroll
            for (int j = 0; j < DIMS / 4; j++) {
                float4 v = xp[j];
                xr[4 * j] = v.x; xr[4 * j + 1] = v.y;
                xr[4 * j + 2] = v.z; xr[4 * j + 3] = v.w;
            }
        }
        double xs;
        {
            float a = __ldg(x + (size_t)row * DIMS + 2 * lane);
            float b = __ldg(x + (size_t)row * DIMS + 2 * lane + 1);
            xs = (double)a * a + (double)b * b;
            #pragma unroll
            for (int off = 16; off > 0; off >>= 1)
                xs += __shfl_xor_sync(0xffffffffu, xs, off);
        }
        const float xnorm = (float)xs;

        float best = FLT_MAX;
        int   bi   = 0x7fffffff;
        for (int j = 0; j < NCHUNK; j++) {
            float cma = __shfl_sync(0xffffffffu, c0, j & 31);
            float cmb = __shfl_sync(0xffffffffu, c1, j & 31);
            float cm  = (j < 32) ? cma : cmb;
            if (cm < thr) continue;

            const int k0 = j * GN + lane;
            const int k1 = k0 + 32;
            const float4* e0 = (const float4*)(cb + (size_t)k0 * DIMS);
            const float4* e1 = (const float4*)(cb + (size_t)k1 * DIMS);
            float a0 = 0.0f, a1 = 0.0f;
            #pragma unroll
            for (int qd = 0; qd < DIMS / 4; qd++) {
                float4 E0 = e0[qd];
                float4 E1 = e1[qd];
                a0 = fmaf(xr[4 * qd + 0], E0.x, a0);
                a0 = fmaf(xr[4 * qd + 1], E0.y, a0);
                a0 = fmaf(xr[4 * qd + 2], E0.z, a0);
                a0 = fmaf(xr[4 * qd + 3], E0.w, a0);
                a1 = fmaf(xr[4 * qd + 0], E1.x, a1);
                a1 = fmaf(xr[4 * qd + 1], E1.y, a1);
                a1 = fmaf(xr[4 * qd + 2], E1.z, a1);
                a1 = fmaf(xr[4 * qd + 3], E1.w, a1);
            }
            float d0 = (xnorm + __ldg(&g_enorm[k0])) - 2.0f * a0;
            float d1 = (xnorm + __ldg(&g_enorm[k1])) - 2.0f * a1;
            if (d0 < best) { best = d0; bi = k0; }
            if (d1 < best) { best = d1; bi = k1; }
        }
        #pragma unroll
        for (int s = 1; s < 32; s <<= 1) {
            float ob = __shfl_xor_sync(0xffffffffu, best, s);
            int   oi = __shfl_xor_sync(0xffffffffu, bi,   s);
            if (ob < best || (ob == best && oi < bi)) { best = ob; bi = oi; }
        }
        if (lane == 0) g_idx[row] = bi;
    }
}

// ---------- epilogue: gather winner, straight-through output, loss partials ----------
__global__ __launch_bounds__(ETHREADS)
void vq_epi(const float* __restrict__ x, const float* __restrict__ y,
            const float* __restrict__ cb, float* __restrict__ out) {
    __shared__ float s_red[ETHREADS / 32];

    const int tid = threadIdx.x;
    const int row = blockIdx.x * ETHREADS + tid;
    const int bidx = g_idx[row];

    float ls = 0.f;
    const float4* xp = (const float4*)(x  + (size_t)row  * DIMS);
    const float4* yp = (const float4*)(y  + (size_t)row  * DIMS);
    const float4* ep = (const float4*)(cb + (size_t)bidx * DIMS);
    float4*       op = (float4*)(out + (size_t)row * DIMS);

    #pragma unroll
    for (int i = 0; i < DIMS / 4; i++) {
        float4 xv = xp[i];
        float4 yv = yp[i];
        float4 e  = ep[i];

        float d;
        d = e.x - xv.x; ls += d * d;  d = e.x - yv.x; ls += d * d;
        d = e.y - xv.y; ls += d * d;  d = e.y - yv.y; ls += d * d;
        d = e.z - xv.z; ls += d * d;  d = e.z - yv.z; ls += d * d;
        d = e.w - xv.w; ls += d * d;  d = e.w - yv.w; ls += d * d;

        float4 o;
        float a;
        a = xv.x + yv.x; o.x = a + (e.x - a);
        a = xv.y + yv.y; o.y = a + (e.y - a);
        a = xv.z + yv.z; o.z = a + (e.z - a);
        a = xv.w + yv.w; o.w = a + (e.w - a);
        op[i] = o;
    }

    #pragma unroll
    for (int off = 16; off > 0; off >>= 1)
        ls += __shfl_xor_sync(0xffffffffu, ls, off);
    if ((tid & 31) == 0) s_red[tid >> 5] = ls;
    __syncthreads();
    if (tid == 0) {
        float s = 0.f;
        #pragma unroll
        for (int w = 0; w < ETHREADS / 32; w++) s += s_red[w];
        g_bsum[blockIdx.x] = s;
    }
}

__global__ void vq_fin(float* __restrict__ out) {
    if (threadIdx.x == 0 && blockIdx.x == 0) {
        double acc = 0.0;
        for (int i = 0; i < EBLOCKS; i++) acc += (double)g_bsum[i];
        double loss = 1.25 * acc / (double)((size_t)N_ROWS * DIMS);
        out[(size_t)N_ROWS * DIMS] = (float)loss;
    }
}

extern "C" void kernel_launch(void* const* d_in, const int* in_sizes, int n_in,
                              void* d_out, int out_size) {
    const float* x  = (const float*)d_in[0];
    const float* y  = (const float*)d_in[1];
    const float* cb = (const float*)d_in[2];
    float* out = (float*)d_out;

    static int smem_set = 0;
    if (!smem_set) {
        cudaFuncSetAttribute(vq_gemm1, cudaFuncAttributeMaxDynamicSharedMemorySize, SMEM1_TOTAL);
        smem_set = 1;
    }

    vq_init<<<(KENT + 255) / 256, 256>>>(cb);
    vq_prep_cb<<<(KENT * DIMS / 4 + 255) / 256, 256>>>(cb);
    vq_gemm1<<<GBLOCKS, 256, SMEM1_TOTAL>>>(x);
    vq_cand<<<256, 256>>>(x, cb);
    vq_epi<<<EBLOCKS, ETHREADS>>>(x, y, cb, out);
    vq_fin<<<1, 1>>>(out);
}